// round 1
// baseline (speedup 1.0000x reference)
#include <cuda_runtime.h>
#include <math.h>

#define N384 384
#define NPIX (384*384)   // 147456

__device__ __forceinline__ float2 cmul(float2 a, float2 b) {
    return make_float2(a.x*b.x - a.y*b.y, a.x*b.y + a.y*b.x);
}

// ---------------- scratch (static device globals; no allocation) ----------------
__device__ float2 g_Tmp[36 * NPIX];   // ping scratch (forward uses 12 planes, inverse 36)
__device__ float2 g_Y  [12 * NPIX];   // x_freq_shift (relabeled): [b',c',h',w']
__device__ float2 g_Att[ 4 * NPIX];   // attended [b,h,w] complex
__device__ float  g_XF [36 * NPIX];   // x_filtered planes, indexed by OUTPUT (co,b2,ci)
__device__ float  g_XSP[12 * NPIX];   // spatial conv [b,co,h,w]

// ---------------- 384-point FFT: N = 3 * 128 (Cooley-Tukey) ----------------
// Layout: data in shared sa[384]. Called by all 192 threads of the block.
// DIR = -1 forward (e^{-2pi i nk/N}), +1 inverse (unscaled).
template<int DIR>
__device__ void fft384(float2* sa, int tid) {
    __syncthreads();
    // permute: a[n2*128 + j] = x[3*brev7(j) + n2]
    int idx0 = tid, idx1 = tid + 192;
    int j0 = idx0 & 127, n20 = idx0 >> 7;
    int j1 = idx1 & 127, n21 = idx1 >> 7;
    int r0 = __brev((unsigned)j0) >> 25;
    int r1 = __brev((unsigned)j1) >> 25;
    float2 v0 = sa[3*r0 + n20];
    float2 v1 = sa[3*r1 + n21];
    __syncthreads();
    sa[idx0] = v0; sa[idx1] = v1;
    __syncthreads();

    // three 128-pt radix-2 DIT FFTs; thread t: subseq n2 = t/64, butterfly tb = t%64
    int n2 = tid / 64;
    int tb = tid % 64;
    #pragma unroll
    for (int len = 2; len <= 128; len <<= 1) {
        int half = len >> 1;
        int blk  = tb / half;
        int j    = tb - blk*half;
        int base = n2*128 + blk*len + j;
        float s, c;
        sincospif(2.0f * DIR * (float)j / (float)len, &s, &c);
        float2 w = make_float2(c, s);
        float2 u = sa[base];
        float2 t = cmul(sa[base + half], w);
        sa[base]        = make_float2(u.x + t.x, u.y + t.y);
        sa[base + half] = make_float2(u.x - t.x, u.y - t.y);
        __syncthreads();
    }

    // radix-3 combine: X[k1 + 128*k2] = sum_{n2} A_{n2}[k1] * W384^{n2 k1} * W3^{n2 k2}
    if (tid < 128) {
        int k1 = tid;
        float2 t0 = sa[k1];
        float2 t1 = sa[128 + k1];
        float2 t2 = sa[256 + k1];
        float s, c;
        sincospif(2.0f * DIR * (float)k1 / 384.0f, &s, &c);
        t1 = cmul(t1, make_float2(c, s));
        sincospif(2.0f * DIR * (float)(2*k1) / 384.0f, &s, &c);
        t2 = cmul(t2, make_float2(c, s));
        const float c3 = -0.5f;
        const float s3 = DIR * 0.86602540378443864676f; // sin(2*pi/3)*DIR
        float2 w3  = make_float2(c3,  s3);   // e^{2pi i DIR/3}
        float2 w3b = make_float2(c3, -s3);   // e^{4pi i DIR/3}
        float2 x0 = make_float2(t0.x + t1.x + t2.x, t0.y + t1.y + t2.y);
        float2 a1 = cmul(t1, w3),  a2 = cmul(t2, w3b);
        float2 x1 = make_float2(t0.x + a1.x + a2.x, t0.y + a1.y + a2.y);
        float2 b1 = cmul(t1, w3b), b2 = cmul(t2, w3);
        float2 x2 = make_float2(t0.x + b1.x + b2.x, t0.y + b1.y + b2.y);
        sa[k1]       = x0;
        sa[128 + k1] = x1;
        sa[256 + k1] = x2;
    }
    __syncthreads();
}

// ---------------- forward FFT, rows ----------------
__global__ void k_fwd_rows(const float* __restrict__ x) {
    __shared__ float2 sa[384];
    int bh = blockIdx.x;
    int h = bh % 384, p = bh / 384;           // p = b*3 + c, 12 planes
    int tid = threadIdx.x;                     // 192
    const float* row = x + (size_t)p*NPIX + (size_t)h*384;
    sa[tid]       = make_float2(row[tid],       0.0f);
    sa[tid + 192] = make_float2(row[tid + 192], 0.0f);
    fft384<-1>(sa, tid);
    float2* o = g_Tmp + (size_t)p*NPIX + (size_t)h*384;
    o[tid] = sa[tid]; o[tid + 192] = sa[tid + 192];
}

// ---------------- forward FFT, cols + full fftshift + batch/channel relabel ----------------
__global__ void k_fwd_cols() {
    __shared__ float2 sa[384];
    int bw = blockIdx.x;
    int w = bw % 384, p = bw / 384;
    int b = p / 3, c = p % 3;
    int tid = threadIdx.x;
    const float2* col = g_Tmp + (size_t)p*NPIX + w;
    sa[tid]       = col[(size_t)tid * 384];
    sa[tid + 192] = col[(size_t)(tid + 192) * 384];
    fft384<-1>(sa, tid);
    // fftshift over ALL axes: Xhat[b,c,h,w] -> Y[(b+2)%4, (c+1)%3, (h+192)%384, (w+192)%384]
    int pp = ((b + 2) & 3) * 3 + ((c + 1) % 3);
    int wp = (w + 192) % 384;
    float2* o = g_Y + (size_t)pp*NPIX + wp;
    int h0 = tid, h1 = tid + 192;
    o[(size_t)((h0 + 192) % 384) * 384] = sa[h0];
    o[(size_t)((h1 + 192) % 384) * 384] = sa[h1];
}

// ---------------- fused: log-Gabor bank + attention MLP + softmax + wgt + attended ----------------
__global__ void k_attn(const float* __restrict__ theta, const float* __restrict__ sigma,
                       const float* __restrict__ f0,    const float* __restrict__ theta0,
                       const float* __restrict__ w1,    const float* __restrict__ b1v,
                       const float* __restrict__ w2,    const float* __restrict__ b2v) {
    __shared__ float sW1[192], sB1[64], sW2[576], sB2[9];
    __shared__ float sLF0[27], sI2LS[27], sTH[27], sI2T0[27];
    int tid = threadIdx.x;  // 256
    for (int i = tid; i < 192; i += 256) sW1[i] = w1[i];
    for (int i = tid; i < 64;  i += 256) sB1[i] = b1v[i];
    for (int i = tid; i < 576; i += 256) sW2[i] = w2[i];
    if (tid < 9)  sB2[tid] = b2v[tid];
    if (tid < 27) {
        sLF0[tid] = logf(f0[tid]);
        float ls = logf(sigma[tid]);
        sI2LS[tid] = 1.0f / (2.0f * ls * ls);
        sTH[tid]   = theta[tid];
        float t0 = theta0[tid];
        sI2T0[tid] = 1.0f / (2.0f * t0 * t0);
    }
    __syncthreads();

    int px = blockIdx.x * 256 + tid;
    if (px >= NPIX) return;
    int h = px / 384, w = px % 384;
    float yy = -1.0f + 2.0f * (float)h / 383.0f;
    float xx = -1.0f + 2.0f * (float)w / 383.0f;
    float r   = sqrtf(xx*xx + yy*yy + 1e-6f);
    float phi = atan2f(yy, xx);

    // filt[(s*3+co)*3 + d] : independent of batch
    float filt[27];
    #pragma unroll
    for (int i = 0; i < 27; i++) {
        float L  = logf(r - sLF0[i]);
        float dp = phi - sTH[i];
        filt[i] = expf(-(L*L*sI2LS[i] + dp*dp*sI2T0[i]));
    }

    for (int b = 0; b < 4; b++) {
        float2 yv[3]; float mag[3];
        #pragma unroll
        for (int d = 0; d < 3; d++) {
            yv[d] = g_Y[(size_t)(b*3 + d)*NPIX + px];
            mag[d] = sqrtf(yv[d].x*yv[d].x + yv[d].y*yv[d].y);
        }
        float logit[9];
        #pragma unroll
        for (int o = 0; o < 9; o++) logit[o] = sB2[o];
        for (int j = 0; j < 64; j++) {
            float hj = sB1[j] + sW1[j*3]*mag[0] + sW1[j*3+1]*mag[1] + sW1[j*3+2]*mag[2];
            hj = fmaxf(hj, 0.0f);
            #pragma unroll
            for (int o = 0; o < 9; o++) logit[o] += sW2[o*64 + j] * hj;
        }
        float mx = logit[0];
        #pragma unroll
        for (int o = 1; o < 9; o++) mx = fmaxf(mx, logit[o]);
        float ex[9]; float se = 0.0f;
        #pragma unroll
        for (int o = 0; o < 9; o++) { ex[o] = expf(logit[o] - mx); se += ex[o]; }
        float inv = 1.0f / se;

        float2 acc = make_float2(0.0f, 0.0f);
        #pragma unroll
        for (int d = 0; d < 3; d++) {
            float wg = 0.0f;
            #pragma unroll
            for (int o = 0; o < 9; o++) wg += ex[o] * filt[o*3 + d];
            wg *= inv;
            acc.x += yv[d].x * wg;
            acc.y += yv[d].y * wg;
        }
        g_Att[(size_t)b*NPIX + px] = acc;
    }
}

// ---------------- inverse FFT rows of ifftshift(mask * attended) ----------------
// Plane q indexed by OUTPUT triple (co,b2,ci): q = (co*4+b2)*3+ci.
// Source: cos=(co+1)%3, bs=(b2+2)%4, cis=(ci+1)%3 (from ifftshift on axes 1..3).
__global__ void k_ifft_rows(const float* __restrict__ band) {
    __shared__ float2 sa[384];
    int bh = blockIdx.x;
    int h = bh % 384, q = bh / 384;
    int ci = q % 3, b2 = (q / 3) & 3, co = q / 12;
    int cos_ = (co + 1) % 3, bs = (b2 + 2) & 3, cis = (ci + 1) % 3;
    int bi = (cos_*3 + cis) * 2;
    int si = (int)floorf((band[bi]     + 1.0f) / 2.0f * 384.0f);
    int ei = (int)floorf((band[bi + 1] + 1.0f) / 2.0f * 384.0f);
    int hs = (h + 192) % 384;                 // ifftshift on h
    bool active = (si < ei) && (hs >= si) && (hs < ei);
    int tid = threadIdx.x;
    float2* o = g_Tmp + (size_t)q*NPIX + (size_t)h*384;
    if (!active) {                            // entire row is zero -> skip FFT
        float2 z = make_float2(0.0f, 0.0f);
        o[tid] = z; o[tid + 192] = z;
        return;
    }
    const float2* arow = g_Att + (size_t)bs*NPIX + (size_t)hs*384;
    #pragma unroll
    for (int k = 0; k < 2; k++) {
        int w  = tid + k*192;
        int ws = (w + 192) % 384;             // ifftshift on w
        bool on = (ws >= si) && (ws < ei);
        sa[w] = on ? arow[ws] : make_float2(0.0f, 0.0f);
    }
    fft384<1>(sa, tid);
    o[tid] = sa[tid]; o[tid + 192] = sa[tid + 192];
}

// ---------------- inverse FFT cols, take real, scale 1/N^2 ----------------
__global__ void k_ifft_cols() {
    __shared__ float2 sa[384];
    int bw = blockIdx.x;
    int w = bw % 384, q = bw / 384;
    int tid = threadIdx.x;
    const float2* col = g_Tmp + (size_t)q*NPIX + w;
    sa[tid]       = col[(size_t)tid * 384];
    sa[tid + 192] = col[(size_t)(tid + 192) * 384];
    fft384<1>(sa, tid);
    const float sc = 1.0f / (384.0f * 384.0f);
    float* o = g_XF + (size_t)q*NPIX + w;
    o[(size_t)tid * 384]         = sa[tid].x * sc;
    o[(size_t)(tid + 192) * 384] = sa[tid + 192].x * sc;
}

// ---------------- 3x3 spatial conv (cross-correlation, pad 1) ----------------
__global__ void k_conv(const float* __restrict__ x, const float* __restrict__ cw) {
    __shared__ float sw[81];
    if (threadIdx.x < 81) sw[threadIdx.x] = cw[threadIdx.x];
    __syncthreads();
    int idx = blockIdx.x * blockDim.x + threadIdx.x;
    if (idx >= 12 * NPIX) return;
    int w = idx % 384;
    int h = (idx / 384) % 384;
    int p = idx / NPIX;            // p = b*3 + co
    int co = p % 3, b = p / 3;
    float acc = 0.0f;
    #pragma unroll
    for (int cin = 0; cin < 3; cin++) {
        const float* xp = x + (size_t)(b*3 + cin)*NPIX;
        #pragma unroll
        for (int kh = 0; kh < 3; kh++) {
            int hh = h + kh - 1;
            if (hh < 0 || hh >= 384) continue;
            #pragma unroll
            for (int kw = 0; kw < 3; kw++) {
                int ww = w + kw - 1;
                if (ww < 0 || ww >= 384) continue;
                acc += xp[(size_t)hh*384 + ww] * sw[((co*3 + cin)*3 + kh)*3 + kw];
            }
        }
    }
    g_XSP[idx] = acc;
}

// ---------------- combine + broadcast over b1 ----------------
__global__ void k_combine(const float* __restrict__ mixing, float* __restrict__ out) {
    size_t idx = (size_t)blockIdx.x * blockDim.x + threadIdx.x;
    const size_t NIN = (size_t)36 * NPIX;
    if (idx >= NIN) return;
    float mix = mixing[0];
    size_t px = idx % NPIX;
    int t = (int)(idx / NPIX);     // (co*4 + b2)*3 + ci
    int ci = t % 3, b2 = (t / 3) & 3;
    float xf = g_XF[idx];
    float xs = g_XSP[(size_t)(b2*3 + ci)*NPIX + px];
    float val = mix * xf + (1.0f - mix) * xs;
    #pragma unroll
    for (int b1 = 0; b1 < 4; b1++) out[(size_t)b1 * NIN + idx] = val;
}

// ---------------- launch ----------------
extern "C" void kernel_launch(void* const* d_in, const int* in_sizes, int n_in,
                              void* d_out, int out_size) {
    const float* x      = (const float*)d_in[0];
    const float* theta  = (const float*)d_in[1];
    const float* sigma  = (const float*)d_in[2];
    const float* f0     = (const float*)d_in[3];
    const float* theta0 = (const float*)d_in[4];
    const float* w1     = (const float*)d_in[5];
    const float* b1v    = (const float*)d_in[6];
    const float* w2     = (const float*)d_in[7];
    const float* b2v    = (const float*)d_in[8];
    const float* convw  = (const float*)d_in[9];
    const float* mixing = (const float*)d_in[10];
    const float* band   = (const float*)d_in[11];
    float* out = (float*)d_out;

    k_fwd_rows<<<12 * 384, 192>>>(x);
    k_fwd_cols<<<12 * 384, 192>>>();
    k_attn<<<NPIX / 256, 256>>>(theta, sigma, f0, theta0, w1, b1v, w2, b2v);
    k_ifft_rows<<<36 * 384, 192>>>(band);
    k_ifft_cols<<<36 * 384, 192>>>();
    k_conv<<<(12 * NPIX + 255) / 256, 256>>>(x, convw);
    k_combine<<<(36 * NPIX + 255) / 256, 256>>>(mixing, out);
}

// round 2
// speedup vs baseline: 1.4705x; 1.4705x over previous
#include <cuda_runtime.h>
#include <math.h>

#define NPIX (384*384)   // 147456
#define TC 8             // columns per tile in column-FFT kernels

__device__ __forceinline__ float2 cmul(float2 a, float2 b) {
    return make_float2(a.x*b.x - a.y*b.y, a.x*b.y + a.y*b.x);
}

// ---------------- scratch (static device globals; no allocation) ----------------
__device__ float2 g_Tmp[36 * NPIX];   // ping scratch (forward uses 12 planes, inverse 36)
__device__ float2 g_Y  [12 * NPIX];   // x_freq_shift (shifted + relabeled): [b',c',h',w']
__device__ float2 g_Att[ 4 * NPIX];   // attended [b,h,w] complex
__device__ float  g_XSP[12 * NPIX];   // spatial conv [b,co,h,w]
__device__ float2 g_TW [384];         // twiddle: TW[k] = e^{-2*pi*i*k/384}

// ---------------- twiddle table ----------------
__global__ void k_twiddle() {
    int k = threadIdx.x;   // 384
    float s, c;
    sincospif(2.0f * (float)k / 384.0f, &s, &c);
    g_TW[k] = make_float2(c, -s);
}

// ---------------- 384-pt FFT on one row in shared (192 threads) ----------------
// DIR = -1 forward, +1 inverse (unscaled). tw = e^{-2pi i k/384} table in shared.
template<int DIR>
__device__ void fft384_row(float2* sa, const float2* tw, int tid) {
    __syncthreads();
    // permute: a[n2*128 + j] = x[3*brev7(j) + n2]  (register staging)
    int idx0 = tid, idx1 = tid + 192;
    int j0 = idx0 & 127, n20 = idx0 >> 7;
    int j1 = idx1 & 127, n21 = idx1 >> 7;
    int r0 = __brev((unsigned)j0) >> 25;
    int r1 = __brev((unsigned)j1) >> 25;
    float2 v0 = sa[3*r0 + n20];
    float2 v1 = sa[3*r1 + n21];
    __syncthreads();
    sa[idx0] = v0; sa[idx1] = v1;
    __syncthreads();

    int n2 = tid / 64;
    int tb = tid % 64;
    int m = 192;                     // 384 / len
    #pragma unroll
    for (int len = 2; len <= 128; len <<= 1, m >>= 1) {
        int half = len >> 1;
        int blk  = tb / half;
        int j    = tb - blk*half;
        int base = n2*128 + blk*len + j;
        float2 w = tw[j * m];
        if (DIR > 0) w.y = -w.y;
        float2 u = sa[base];
        float2 t = cmul(sa[base + half], w);
        sa[base]        = make_float2(u.x + t.x, u.y + t.y);
        sa[base + half] = make_float2(u.x - t.x, u.y - t.y);
        __syncthreads();
    }

    if (tid < 128) {
        int k1 = tid;
        float2 t0 = sa[k1];
        float2 t1 = sa[128 + k1];
        float2 t2 = sa[256 + k1];
        float2 w1 = tw[k1], w2 = tw[2*k1];
        if (DIR > 0) { w1.y = -w1.y; w2.y = -w2.y; }
        t1 = cmul(t1, w1);
        t2 = cmul(t2, w2);
        const float s3 = DIR * 0.86602540378443864676f;
        float2 w3  = make_float2(-0.5f,  s3);
        float2 w3b = make_float2(-0.5f, -s3);
        float2 a1 = cmul(t1, w3),  a2 = cmul(t2, w3b);
        float2 b1 = cmul(t1, w3b), b2 = cmul(t2, w3);
        sa[k1]       = make_float2(t0.x + t1.x + t2.x, t0.y + t1.y + t2.y);
        sa[128 + k1] = make_float2(t0.x + a1.x + a2.x, t0.y + a1.y + a2.y);
        sa[256 + k1] = make_float2(t0.x + b1.x + b2.x, t0.y + b1.y + b2.y);
    }
    __syncthreads();
}

// ---------------- 384-pt FFT over TC=8 columns in shared (256 threads) ----------------
// Data must already be loaded in permuted (bit-reversed) order: slot t*8+c.
template<int DIR>
__device__ void fft384_cols8(float2* sa, const float2* tw, int tid) {
    int m = 192;
    #pragma unroll
    for (int len = 2; len <= 128; len <<= 1, m >>= 1) {
        int half = len >> 1;
        #pragma unroll
        for (int it = 0; it < 6; it++) {           // 192*8/256
            int idx = tid + it*256;
            int cc = idx & 7, t = idx >> 3;
            int n2 = t >> 6, tb = t & 63;
            int blk = tb / half;
            int j   = tb - blk*half;
            int b0  = (n2*128 + blk*len + j)*8 + cc;
            float2 w = tw[j * m];
            if (DIR > 0) w.y = -w.y;
            float2 u = sa[b0];
            float2 t2 = cmul(sa[b0 + half*8], w);
            sa[b0]          = make_float2(u.x + t2.x, u.y + t2.y);
            sa[b0 + half*8] = make_float2(u.x - t2.x, u.y - t2.y);
        }
        __syncthreads();
    }
    #pragma unroll
    for (int it = 0; it < 4; it++) {               // 128*8/256
        int idx = tid + it*256;
        int cc = idx & 7, k1 = idx >> 3;
        float2 t0 = sa[k1*8 + cc];
        float2 t1 = sa[(128 + k1)*8 + cc];
        float2 t2 = sa[(256 + k1)*8 + cc];
        float2 w1 = tw[k1], w2 = tw[2*k1];
        if (DIR > 0) { w1.y = -w1.y; w2.y = -w2.y; }
        t1 = cmul(t1, w1);
        t2 = cmul(t2, w2);
        const float s3 = DIR * 0.86602540378443864676f;
        float2 w3  = make_float2(-0.5f,  s3);
        float2 w3b = make_float2(-0.5f, -s3);
        float2 a1 = cmul(t1, w3),  a2 = cmul(t2, w3b);
        float2 b1 = cmul(t1, w3b), b2 = cmul(t2, w3);
        sa[k1*8 + cc]         = make_float2(t0.x + t1.x + t2.x, t0.y + t1.y + t2.y);
        sa[(128 + k1)*8 + cc] = make_float2(t0.x + a1.x + a2.x, t0.y + a1.y + a2.y);
        sa[(256 + k1)*8 + cc] = make_float2(t0.x + b1.x + b2.x, t0.y + b1.y + b2.y);
    }
    __syncthreads();
}

// ---------------- forward FFT, rows ----------------
__global__ void k_fwd_rows(const float* __restrict__ x) {
    __shared__ float2 sa[384];
    __shared__ float2 tw[384];
    int bh = blockIdx.x;
    int h = bh % 384, p = bh / 384;           // p = b*3 + c, 12 planes
    int tid = threadIdx.x;                     // 192
    tw[tid] = g_TW[tid]; tw[tid + 192] = g_TW[tid + 192];
    const float* row = x + (size_t)p*NPIX + (size_t)h*384;
    sa[tid]       = make_float2(row[tid],       0.0f);
    sa[tid + 192] = make_float2(row[tid + 192], 0.0f);
    fft384_row<-1>(sa, tw, tid);
    float2* o = g_Tmp + (size_t)p*NPIX + (size_t)h*384;
    o[tid] = sa[tid]; o[tid + 192] = sa[tid + 192];
}

// ---------------- forward FFT, cols (tiled) + fftshift + batch/channel relabel ----------------
__global__ void k_fwd_cols() {
    __shared__ float2 sa[384 * TC];
    __shared__ float2 tw[384];
    int tile = blockIdx.x % 48, p = blockIdx.x / 48;
    int b = p / 3, c = p % 3;
    int w0 = tile * TC;
    int tid = threadIdx.x;                     // 256
    for (int i = tid; i < 384; i += 256) tw[i] = g_TW[i];
    // load bit-reversed directly from global (coalesced 64B chunks per row)
    for (int i = tid; i < 384*TC; i += 256) {
        int cc = i & 7, t = i >> 3;
        int j = t & 127, n2 = t >> 7;
        int r = __brev((unsigned)j) >> 25;
        int hsrc = 3*r + n2;
        sa[i] = g_Tmp[(size_t)p*NPIX + (size_t)hsrc*384 + w0 + cc];
    }
    __syncthreads();
    fft384_cols8<-1>(sa, tw, tid);
    // fftshift all axes: X[b,c,h,w] -> Y[(b+2)%4, (c+1)%3, (h+192)%384, (w+192)%384]
    int pp = ((b + 2) & 3) * 3 + ((c + 1) % 3);
    int wp0 = (w0 + 192) % 384;               // tile-aligned, no wrap inside tile
    for (int i = tid; i < 384*TC; i += 256) {
        int cc = i & 7, h = i >> 3;
        int hp = (h + 192) % 384;
        g_Y[(size_t)pp*NPIX + (size_t)hp*384 + wp0 + cc] = sa[i];
    }
}

// ---------------- fused: log-Gabor bank + attention MLP + softmax + wgt + attended ----------------
__global__ void k_attn(const float* __restrict__ theta, const float* __restrict__ sigma,
                       const float* __restrict__ f0,    const float* __restrict__ theta0,
                       const float* __restrict__ w1,    const float* __restrict__ b1v,
                       const float* __restrict__ w2,    const float* __restrict__ b2v) {
    __shared__ float sW1[192], sB1[64], sW2[576], sB2[9];
    __shared__ float sLF0[27], sI2LS[27], sTH[27], sI2T0[27];
    int tid = threadIdx.x;  // 256
    for (int i = tid; i < 192; i += 256) sW1[i] = w1[i];
    for (int i = tid; i < 64;  i += 256) sB1[i] = b1v[i];
    for (int i = tid; i < 576; i += 256) sW2[i] = w2[i];
    if (tid < 9)  sB2[tid] = b2v[tid];
    if (tid < 27) {
        sLF0[tid] = logf(f0[tid]);
        float ls = logf(sigma[tid]);
        sI2LS[tid] = 1.0f / (2.0f * ls * ls);
        sTH[tid]   = theta[tid];
        float t0 = theta0[tid];
        sI2T0[tid] = 1.0f / (2.0f * t0 * t0);
    }
    __syncthreads();

    int px = blockIdx.x * 256 + tid;
    if (px >= NPIX) return;
    int h = px / 384, w = px % 384;
    float yy = -1.0f + 2.0f * (float)h / 383.0f;
    float xx = -1.0f + 2.0f * (float)w / 383.0f;
    float r   = sqrtf(xx*xx + yy*yy + 1e-6f);
    float phi = atan2f(yy, xx);

    float filt[27];
    #pragma unroll
    for (int i = 0; i < 27; i++) {
        float L  = logf(r - sLF0[i]);
        float dp = phi - sTH[i];
        filt[i] = expf(-(L*L*sI2LS[i] + dp*dp*sI2T0[i]));
    }

    for (int b = 0; b < 4; b++) {
        float2 yv[3]; float mag[3];
        #pragma unroll
        for (int d = 0; d < 3; d++) {
            yv[d] = g_Y[(size_t)(b*3 + d)*NPIX + px];
            mag[d] = sqrtf(yv[d].x*yv[d].x + yv[d].y*yv[d].y);
        }
        float logit[9];
        #pragma unroll
        for (int o = 0; o < 9; o++) logit[o] = sB2[o];
        for (int j = 0; j < 64; j++) {
            float hj = sB1[j] + sW1[j*3]*mag[0] + sW1[j*3+1]*mag[1] + sW1[j*3+2]*mag[2];
            hj = fmaxf(hj, 0.0f);
            #pragma unroll
            for (int o = 0; o < 9; o++) logit[o] += sW2[o*64 + j] * hj;
        }
        float mx = logit[0];
        #pragma unroll
        for (int o = 1; o < 9; o++) mx = fmaxf(mx, logit[o]);
        float ex[9]; float se = 0.0f;
        #pragma unroll
        for (int o = 0; o < 9; o++) { ex[o] = expf(logit[o] - mx); se += ex[o]; }
        float inv = 1.0f / se;

        float2 acc = make_float2(0.0f, 0.0f);
        #pragma unroll
        for (int d = 0; d < 3; d++) {
            float wg = 0.0f;
            #pragma unroll
            for (int o = 0; o < 9; o++) wg += ex[o] * filt[o*3 + d];
            wg *= inv;
            acc.x += yv[d].x * wg;
            acc.y += yv[d].y * wg;
        }
        g_Att[(size_t)b*NPIX + px] = acc;
    }
}

// ---------------- inverse FFT rows of ifftshift(mask * attended) ----------------
// Plane q = (co*4+b2)*3+ci. Only rows h in [si-192, ei-192) (subset of [0,192))
// are nonzero — other rows are never written; the column pass reconstructs zeros.
__global__ void k_ifft_rows(const float* __restrict__ band) {
    __shared__ float2 sa[384];
    __shared__ float2 tw[384];
    int bh = blockIdx.x;
    int h = bh % 192, q = bh / 192;
    int ci = q % 3, b2 = (q / 3) & 3, co = q / 12;
    int cos_ = (co + 1) % 3, bs = (b2 + 2) & 3, cis = (ci + 1) % 3;
    int bi = (cos_*3 + cis) * 2;
    int si = (int)floorf((band[bi]     + 1.0f) / 2.0f * 384.0f);
    int ei = (int)floorf((band[bi + 1] + 1.0f) / 2.0f * 384.0f);
    int hs = h + 192;                          // ifftshift on h (h<192 always)
    if (!((si < ei) && (hs >= si) && (hs < ei))) return;   // zero row: skip entirely

    int tid = threadIdx.x;
    tw[tid] = g_TW[tid]; tw[tid + 192] = g_TW[tid + 192];
    const float2* arow = g_Att + (size_t)bs*NPIX + (size_t)hs*384;
    #pragma unroll
    for (int k = 0; k < 2; k++) {
        int w  = tid + k*192;
        int ws = (w + 192) % 384;              // ifftshift on w
        bool on = (ws >= si) && (ws < ei);
        sa[w] = on ? arow[ws] : make_float2(0.0f, 0.0f);
    }
    fft384_row<1>(sa, tw, tid);
    float2* o = g_Tmp + (size_t)q*NPIX + (size_t)h*384;
    o[tid] = sa[tid]; o[tid + 192] = sa[tid + 192];
}

// ---------------- inverse FFT cols (tiled) fused with mix + b1-broadcast write ----------------
__global__ void k_ifft_cols_combine(const float* __restrict__ band,
                                    const float* __restrict__ mixing,
                                    float* __restrict__ out) {
    __shared__ float2 sa[384 * TC];
    __shared__ float2 tw[384];
    int tile = blockIdx.x % 48, q = blockIdx.x / 48;
    int ci = q % 3, b2 = (q / 3) & 3, co = q / 12;
    int cos_ = (co + 1) % 3, cis = (ci + 1) % 3;
    int bi = (cos_*3 + cis) * 2;
    int si = (int)floorf((band[bi]     + 1.0f) / 2.0f * 384.0f);
    int ei = (int)floorf((band[bi + 1] + 1.0f) / 2.0f * 384.0f);
    int h0 = si - 192, h1e = ei - 192;         // active rows in g_Tmp
    int tid = threadIdx.x;                     // 256
    int w0 = tile * TC;
    float mix = mixing[0];
    const float* xsp = g_XSP + (size_t)(b2*3 + ci)*NPIX;
    const size_t NIN = (size_t)36 * NPIX;

    if (si >= ei) {                            // fully-masked plane: x_filtered = 0
        for (int i = tid; i < 384*TC; i += 256) {
            int cc = i & 7, h = i >> 3;
            size_t px = (size_t)h*384 + w0 + cc;
            float val = (1.0f - mix) * xsp[px];
            size_t o = (size_t)q*NPIX + px;
            #pragma unroll
            for (int b1 = 0; b1 < 4; b1++) out[(size_t)b1*NIN + o] = val;
        }
        return;
    }

    for (int i = tid; i < 384; i += 256) tw[i] = g_TW[i];
    for (int i = tid; i < 384*TC; i += 256) {
        int cc = i & 7, t = i >> 3;
        int j = t & 127, n2 = t >> 7;
        int r = __brev((unsigned)j) >> 25;
        int hsrc = 3*r + n2;
        float2 v = make_float2(0.0f, 0.0f);
        if (hsrc >= h0 && hsrc < h1e)
            v = g_Tmp[(size_t)q*NPIX + (size_t)hsrc*384 + w0 + cc];
        sa[i] = v;
    }
    __syncthreads();
    fft384_cols8<1>(sa, tw, tid);

    const float sc = 1.0f / (384.0f * 384.0f);
    for (int i = tid; i < 384*TC; i += 256) {
        int cc = i & 7, h = i >> 3;
        size_t px = (size_t)h*384 + w0 + cc;
        float val = mix * (sa[i].x * sc) + (1.0f - mix) * xsp[px];
        size_t o = (size_t)q*NPIX + px;
        #pragma unroll
        for (int b1 = 0; b1 < 4; b1++) out[(size_t)b1*NIN + o] = val;
    }
}

// ---------------- 3x3 spatial conv (cross-correlation, pad 1) ----------------
__global__ void k_conv(const float* __restrict__ x, const float* __restrict__ cw) {
    __shared__ float sw[81];
    if (threadIdx.x < 81) sw[threadIdx.x] = cw[threadIdx.x];
    __syncthreads();
    int idx = blockIdx.x * blockDim.x + threadIdx.x;
    if (idx >= 12 * NPIX) return;
    int w = idx % 384;
    int h = (idx / 384) % 384;
    int p = idx / NPIX;            // p = b*3 + co
    int co = p % 3, b = p / 3;
    float acc = 0.0f;
    #pragma unroll
    for (int cin = 0; cin < 3; cin++) {
        const float* xp = x + (size_t)(b*3 + cin)*NPIX;
        #pragma unroll
        for (int kh = 0; kh < 3; kh++) {
            int hh = h + kh - 1;
            if (hh < 0 || hh >= 384) continue;
            #pragma unroll
            for (int kw = 0; kw < 3; kw++) {
                int ww = w + kw - 1;
                if (ww < 0 || ww >= 384) continue;
                acc += xp[(size_t)hh*384 + ww] * sw[((co*3 + cin)*3 + kh)*3 + kw];
            }
        }
    }
    g_XSP[idx] = acc;
}

// ---------------- launch ----------------
extern "C" void kernel_launch(void* const* d_in, const int* in_sizes, int n_in,
                              void* d_out, int out_size) {
    const float* x      = (const float*)d_in[0];
    const float* theta  = (const float*)d_in[1];
    const float* sigma  = (const float*)d_in[2];
    const float* f0     = (const float*)d_in[3];
    const float* theta0 = (const float*)d_in[4];
    const float* w1     = (const float*)d_in[5];
    const float* b1v    = (const float*)d_in[6];
    const float* w2     = (const float*)d_in[7];
    const float* b2v    = (const float*)d_in[8];
    const float* convw  = (const float*)d_in[9];
    const float* mixing = (const float*)d_in[10];
    const float* band   = (const float*)d_in[11];
    float* out = (float*)d_out;

    k_twiddle<<<1, 384>>>();
    k_fwd_rows<<<12 * 384, 192>>>(x);
    k_fwd_cols<<<48 * 12, 256>>>();
    k_attn<<<NPIX / 256, 256>>>(theta, sigma, f0, theta0, w1, b1v, w2, b2v);
    k_conv<<<(12 * NPIX + 255) / 256, 256>>>(x, convw);
    k_ifft_rows<<<36 * 192, 192>>>(band);
    k_ifft_cols_combine<<<48 * 36, 256>>>(band, mixing, out);
}

// round 3
// speedup vs baseline: 1.7571x; 1.1950x over previous
#include <cuda_runtime.h>
#include <math.h>

#define NPIX (384*384)   // 147456
#define TC 8             // columns per tile in column-FFT kernels

__device__ __forceinline__ float2 cmul(float2 a, float2 b) {
    return make_float2(a.x*b.x - a.y*b.y, a.x*b.y + a.y*b.x);
}

// ---------------- scratch (static device globals; no allocation) ----------------
__device__ float2 g_Tmp[36 * NPIX];   // ping scratch (forward uses 12 planes, inverse 36)
__device__ float2 g_Y  [12 * NPIX];   // x_freq_shift (shifted + relabeled): [b',c',h',w']
__device__ float2 g_Att[ 4 * NPIX];   // attended [b,h,w] complex
__device__ float  g_XSP[12 * NPIX];   // spatial conv [b,co,h,w]
__device__ float2 g_TW [384];         // twiddle: TW[k] = e^{-2*pi*i*k/384}

// ---------------- twiddle table ----------------
__global__ void k_twiddle() {
    int k = threadIdx.x;   // 384
    float s, c;
    sincospif(2.0f * (float)k / 384.0f, &s, &c);
    g_TW[k] = make_float2(c, -s);
}

// ---------------- 384-pt FFT on one row in shared (192 threads per row) ----------------
// DIR = -1 forward, +1 inverse (unscaled). tw = e^{-2pi i k/384} table in shared.
// May be called by several row-groups in one block; all groups follow the same
// schedule so the block-wide __syncthreads are uniform.
template<int DIR>
__device__ void fft384_row(float2* sa, const float2* tw, int tid) {
    __syncthreads();
    // permute: a[n2*128 + j] = x[3*brev7(j) + n2]  (register staging)
    int idx0 = tid, idx1 = tid + 192;
    int j0 = idx0 & 127, n20 = idx0 >> 7;
    int j1 = idx1 & 127, n21 = idx1 >> 7;
    int r0 = __brev((unsigned)j0) >> 25;
    int r1 = __brev((unsigned)j1) >> 25;
    float2 v0 = sa[3*r0 + n20];
    float2 v1 = sa[3*r1 + n21];
    __syncthreads();
    sa[idx0] = v0; sa[idx1] = v1;
    __syncthreads();

    int n2 = tid / 64;
    int tb = tid % 64;
    int m = 192;                     // 384 / len
    #pragma unroll
    for (int len = 2; len <= 128; len <<= 1, m >>= 1) {
        int half = len >> 1;
        int blk  = tb / half;
        int j    = tb - blk*half;
        int base = n2*128 + blk*len + j;
        float2 w = tw[j * m];
        if (DIR > 0) w.y = -w.y;
        float2 u = sa[base];
        float2 t = cmul(sa[base + half], w);
        sa[base]        = make_float2(u.x + t.x, u.y + t.y);
        sa[base + half] = make_float2(u.x - t.x, u.y - t.y);
        __syncthreads();
    }

    if (tid < 128) {
        int k1 = tid;
        float2 t0 = sa[k1];
        float2 t1 = sa[128 + k1];
        float2 t2 = sa[256 + k1];
        float2 w1 = tw[k1], w2 = tw[2*k1];
        if (DIR > 0) { w1.y = -w1.y; w2.y = -w2.y; }
        t1 = cmul(t1, w1);
        t2 = cmul(t2, w2);
        const float s3 = DIR * 0.86602540378443864676f;
        float2 w3  = make_float2(-0.5f,  s3);
        float2 w3b = make_float2(-0.5f, -s3);
        float2 a1 = cmul(t1, w3),  a2 = cmul(t2, w3b);
        float2 b1 = cmul(t1, w3b), b2 = cmul(t2, w3);
        sa[k1]       = make_float2(t0.x + t1.x + t2.x, t0.y + t1.y + t2.y);
        sa[128 + k1] = make_float2(t0.x + a1.x + a2.x, t0.y + a1.y + a2.y);
        sa[256 + k1] = make_float2(t0.x + b1.x + b2.x, t0.y + b1.y + b2.y);
    }
    __syncthreads();
}

// ---------------- 384-pt FFT over TC=8 columns in shared (256 threads) ----------------
// Data must already be loaded in permuted (bit-reversed) order: slot t*8+c.
template<int DIR>
__device__ void fft384_cols8(float2* sa, const float2* tw, int tid) {
    int m = 192;
    #pragma unroll
    for (int len = 2; len <= 128; len <<= 1, m >>= 1) {
        int half = len >> 1;
        #pragma unroll
        for (int it = 0; it < 6; it++) {           // 192*8/256
            int idx = tid + it*256;
            int cc = idx & 7, t = idx >> 3;
            int n2 = t >> 6, tb = t & 63;
            int blk = tb / half;
            int j   = tb - blk*half;
            int b0  = (n2*128 + blk*len + j)*8 + cc;
            float2 w = tw[j * m];
            if (DIR > 0) w.y = -w.y;
            float2 u = sa[b0];
            float2 t2 = cmul(sa[b0 + half*8], w);
            sa[b0]          = make_float2(u.x + t2.x, u.y + t2.y);
            sa[b0 + half*8] = make_float2(u.x - t2.x, u.y - t2.y);
        }
        __syncthreads();
    }
    #pragma unroll
    for (int it = 0; it < 4; it++) {               // 128*8/256
        int idx = tid + it*256;
        int cc = idx & 7, k1 = idx >> 3;
        float2 t0 = sa[k1*8 + cc];
        float2 t1 = sa[(128 + k1)*8 + cc];
        float2 t2 = sa[(256 + k1)*8 + cc];
        float2 w1 = tw[k1], w2 = tw[2*k1];
        if (DIR > 0) { w1.y = -w1.y; w2.y = -w2.y; }
        t1 = cmul(t1, w1);
        t2 = cmul(t2, w2);
        const float s3 = DIR * 0.86602540378443864676f;
        float2 w3  = make_float2(-0.5f,  s3);
        float2 w3b = make_float2(-0.5f, -s3);
        float2 a1 = cmul(t1, w3),  a2 = cmul(t2, w3b);
        float2 b1 = cmul(t1, w3b), b2 = cmul(t2, w3);
        sa[k1*8 + cc]         = make_float2(t0.x + t1.x + t2.x, t0.y + t1.y + t2.y);
        sa[(128 + k1)*8 + cc] = make_float2(t0.x + a1.x + a2.x, t0.y + a1.y + a2.y);
        sa[(256 + k1)*8 + cc] = make_float2(t0.x + b1.x + b2.x, t0.y + b1.y + b2.y);
    }
    __syncthreads();
}

// ---------------- forward FFT, rows (4 rows per block) ----------------
__global__ void k_fwd_rows(const float* __restrict__ x) {
    __shared__ float2 sa4[4][384];
    __shared__ float2 tw[384];
    int tid = threadIdx.x;                     // 768
    int rg  = tid / 192;                       // row-group 0..3
    int rt  = tid % 192;                       // tid within row
    if (tid < 384) tw[tid] = g_TW[tid];
    int gr = blockIdx.x * 4 + rg;              // global row 0..4607
    int p = gr / 384, h = gr % 384;            // p = b*3 + c
    float2* sa = sa4[rg];
    const float* row = x + (size_t)p*NPIX + (size_t)h*384;
    sa[rt]       = make_float2(row[rt],       0.0f);
    sa[rt + 192] = make_float2(row[rt + 192], 0.0f);
    fft384_row<-1>(sa, tw, rt);
    float2* o = g_Tmp + (size_t)p*NPIX + (size_t)h*384;
    o[rt] = sa[rt]; o[rt + 192] = sa[rt + 192];
}

// ---------------- forward FFT, cols (tiled) + fftshift + batch/channel relabel ----------------
__global__ void k_fwd_cols() {
    __shared__ float2 sa[384 * TC];
    __shared__ float2 tw[384];
    int tile = blockIdx.x % 48, p = blockIdx.x / 48;
    int b = p / 3, c = p % 3;
    int w0 = tile * TC;
    int tid = threadIdx.x;                     // 256
    for (int i = tid; i < 384; i += 256) tw[i] = g_TW[i];
    for (int i = tid; i < 384*TC; i += 256) {
        int cc = i & 7, t = i >> 3;
        int j = t & 127, n2 = t >> 7;
        int r = __brev((unsigned)j) >> 25;
        int hsrc = 3*r + n2;
        sa[i] = g_Tmp[(size_t)p*NPIX + (size_t)hsrc*384 + w0 + cc];
    }
    __syncthreads();
    fft384_cols8<-1>(sa, tw, tid);
    int pp = ((b + 2) & 3) * 3 + ((c + 1) % 3);
    int wp0 = (w0 + 192) % 384;               // tile-aligned, no wrap inside tile
    for (int i = tid; i < 384*TC; i += 256) {
        int cc = i & 7, h = i >> 3;
        int hp = (h + 192) % 384;
        g_Y[(size_t)pp*NPIX + (size_t)hp*384 + wp0 + cc] = sa[i];
    }
}

// ---------------- fused: attention MLP (all 4 batches per weight fetch) + Gabor + weighting ----------------
__global__ void k_attn(const float* __restrict__ theta, const float* __restrict__ sigma,
                       const float* __restrict__ f0,    const float* __restrict__ theta0,
                       const float* __restrict__ w1,    const float* __restrict__ b1v,
                       const float* __restrict__ w2,    const float* __restrict__ b2v) {
    __shared__ float4 sW1B[64];    // {w1[j][0..2], b1[j]}
    __shared__ float4 sW2T[64*3];  // per j: 9 outputs (padded to 12): comp o = k*4+c
    __shared__ float  sB2[9];
    __shared__ float  sLF0[27], sI2LS[27], sTH[27], sI2T0[27];
    int tid = threadIdx.x;  // 256
    if (tid < 64) {
        sW1B[tid] = make_float4(w1[tid*3], w1[tid*3+1], w1[tid*3+2], b1v[tid]);
        #pragma unroll
        for (int k = 0; k < 3; k++) {
            float4 v;
            v.x = (k*4+0 < 9) ? w2[(k*4+0)*64 + tid] : 0.0f;
            v.y = (k*4+1 < 9) ? w2[(k*4+1)*64 + tid] : 0.0f;
            v.z = (k*4+2 < 9) ? w2[(k*4+2)*64 + tid] : 0.0f;
            v.w = (k*4+3 < 9) ? w2[(k*4+3)*64 + tid] : 0.0f;
            sW2T[tid*3 + k] = v;
        }
    }
    if (tid < 9)  sB2[tid] = b2v[tid];
    if (tid < 27) {
        sLF0[tid] = logf(f0[tid]);
        float ls = logf(sigma[tid]);
        sI2LS[tid] = 1.0f / (2.0f * ls * ls);
        sTH[tid]   = theta[tid];
        float t0 = theta0[tid];
        sI2T0[tid] = 1.0f / (2.0f * t0 * t0);
    }
    __syncthreads();

    int px = blockIdx.x * 256 + tid;
    if (px >= NPIX) return;

    // phase 1: magnitudes for all 4 batches
    float mag[12];
    #pragma unroll
    for (int b = 0; b < 4; b++)
        #pragma unroll
        for (int d = 0; d < 3; d++) {
            float2 yv = g_Y[(size_t)(b*3 + d)*NPIX + px];
            mag[b*3 + d] = sqrtf(yv.x*yv.x + yv.y*yv.y);
        }

    // phase 2: MLP for all 4 batches sharing each weight fetch
    float lg[36];
    #pragma unroll
    for (int b = 0; b < 4; b++)
        #pragma unroll
        for (int o = 0; o < 9; o++) lg[b*9 + o] = sB2[o];
    for (int j = 0; j < 64; j++) {
        float4 wb = sW1B[j];
        float4 wa0 = sW2T[j*3 + 0];
        float4 wa1 = sW2T[j*3 + 1];
        float4 wa2 = sW2T[j*3 + 2];
        #pragma unroll
        for (int b = 0; b < 4; b++) {
            float hj = fmaxf(wb.w + wb.x*mag[b*3] + wb.y*mag[b*3+1] + wb.z*mag[b*3+2], 0.0f);
            lg[b*9+0] += wa0.x*hj; lg[b*9+1] += wa0.y*hj; lg[b*9+2] += wa0.z*hj;
            lg[b*9+3] += wa0.w*hj; lg[b*9+4] += wa1.x*hj; lg[b*9+5] += wa1.y*hj;
            lg[b*9+6] += wa1.z*hj; lg[b*9+7] += wa1.w*hj; lg[b*9+8] += wa2.x*hj;
        }
    }

    // phase 3: log-Gabor filters (geometry only)
    int h = px / 384, w = px % 384;
    float yy = -1.0f + 2.0f * (float)h / 383.0f;
    float xx = -1.0f + 2.0f * (float)w / 383.0f;
    float r   = sqrtf(xx*xx + yy*yy + 1e-6f);
    float phi = atan2f(yy, xx);
    float filt[27];
    #pragma unroll
    for (int i = 0; i < 27; i++) {
        float L  = logf(r - sLF0[i]);
        float dp = phi - sTH[i];
        filt[i] = expf(-(L*L*sI2LS[i] + dp*dp*sI2T0[i]));
    }

    // phase 4: softmax + weighted spectrum, per batch (reload yv; L2-hot)
    #pragma unroll
    for (int b = 0; b < 4; b++) {
        float mx = lg[b*9];
        #pragma unroll
        for (int o = 1; o < 9; o++) mx = fmaxf(mx, lg[b*9 + o]);
        float ex[9]; float se = 0.0f;
        #pragma unroll
        for (int o = 0; o < 9; o++) { ex[o] = expf(lg[b*9 + o] - mx); se += ex[o]; }
        float inv = 1.0f / se;

        float2 acc = make_float2(0.0f, 0.0f);
        #pragma unroll
        for (int d = 0; d < 3; d++) {
            float wg = 0.0f;
            #pragma unroll
            for (int o = 0; o < 9; o++) wg += ex[o] * filt[o*3 + d];
            wg *= inv;
            float2 yv = g_Y[(size_t)(b*3 + d)*NPIX + px];
            acc.x += yv.x * wg;
            acc.y += yv.y * wg;
        }
        g_Att[(size_t)b*NPIX + px] = acc;
    }
}

// ---------------- inverse FFT rows of ifftshift(mask * attended) ----------------
__global__ void k_ifft_rows(const float* __restrict__ band) {
    __shared__ float2 sa[384];
    __shared__ float2 tw[384];
    int bh = blockIdx.x;
    int h = bh % 192, q = bh / 192;
    int ci = q % 3, b2 = (q / 3) & 3, co = q / 12;
    int cos_ = (co + 1) % 3, bs = (b2 + 2) & 3, cis = (ci + 1) % 3;
    int bi = (cos_*3 + cis) * 2;
    int si = (int)floorf((band[bi]     + 1.0f) / 2.0f * 384.0f);
    int ei = (int)floorf((band[bi + 1] + 1.0f) / 2.0f * 384.0f);
    int hs = h + 192;
    if (!((si < ei) && (hs >= si) && (hs < ei))) return;   // zero row: skip entirely

    int tid = threadIdx.x;
    tw[tid] = g_TW[tid]; tw[tid + 192] = g_TW[tid + 192];
    const float2* arow = g_Att + (size_t)bs*NPIX + (size_t)hs*384;
    #pragma unroll
    for (int k = 0; k < 2; k++) {
        int w  = tid + k*192;
        int ws = (w + 192) % 384;
        bool on = (ws >= si) && (ws < ei);
        sa[w] = on ? arow[ws] : make_float2(0.0f, 0.0f);
    }
    fft384_row<1>(sa, tw, tid);
    float2* o = g_Tmp + (size_t)q*NPIX + (size_t)h*384;
    o[tid] = sa[tid]; o[tid + 192] = sa[tid + 192];
}

// ---------------- inverse FFT cols (tiled) fused with mix + b1-broadcast write ----------------
__global__ void k_ifft_cols_combine(const float* __restrict__ band,
                                    const float* __restrict__ mixing,
                                    float* __restrict__ out) {
    __shared__ float2 sa[384 * TC];
    __shared__ float2 tw[384];
    int tile = blockIdx.x % 48, q = blockIdx.x / 48;
    int ci = q % 3, b2 = (q / 3) & 3, co = q / 12;
    int cos_ = (co + 1) % 3, cis = (ci + 1) % 3;
    int bi = (cos_*3 + cis) * 2;
    int si = (int)floorf((band[bi]     + 1.0f) / 2.0f * 384.0f);
    int ei = (int)floorf((band[bi + 1] + 1.0f) / 2.0f * 384.0f);
    int h0 = si - 192, h1e = ei - 192;         // active rows in g_Tmp
    int tid = threadIdx.x;                     // 256
    int w0 = tile * TC;
    float mix = mixing[0];
    const float* xsp = g_XSP + (size_t)(b2*3 + ci)*NPIX;
    const size_t NIN = (size_t)36 * NPIX;

    if (si >= ei) {                            // fully-masked plane: x_filtered = 0
        for (int i = tid; i < 384*TC; i += 256) {
            int cc = i & 7, h = i >> 3;
            size_t px = (size_t)h*384 + w0 + cc;
            float val = (1.0f - mix) * xsp[px];
            size_t o = (size_t)q*NPIX + px;
            #pragma unroll
            for (int b1 = 0; b1 < 4; b1++) out[(size_t)b1*NIN + o] = val;
        }
        return;
    }

    for (int i = tid; i < 384; i += 256) tw[i] = g_TW[i];
    for (int i = tid; i < 384*TC; i += 256) {
        int cc = i & 7, t = i >> 3;
        int j = t & 127, n2 = t >> 7;
        int r = __brev((unsigned)j) >> 25;
        int hsrc = 3*r + n2;
        float2 v = make_float2(0.0f, 0.0f);
        if (hsrc >= h0 && hsrc < h1e)
            v = g_Tmp[(size_t)q*NPIX + (size_t)hsrc*384 + w0 + cc];
        sa[i] = v;
    }
    __syncthreads();
    fft384_cols8<1>(sa, tw, tid);

    const float sc = 1.0f / (384.0f * 384.0f);
    for (int i = tid; i < 384*TC; i += 256) {
        int cc = i & 7, h = i >> 3;
        size_t px = (size_t)h*384 + w0 + cc;
        float val = mix * (sa[i].x * sc) + (1.0f - mix) * xsp[px];
        size_t o = (size_t)q*NPIX + px;
        #pragma unroll
        for (int b1 = 0; b1 < 4; b1++) out[(size_t)b1*NIN + o] = val;
    }
}

// ---------------- 3x3 spatial conv (cross-correlation, pad 1) ----------------
__global__ void k_conv(const float* __restrict__ x, const float* __restrict__ cw) {
    __shared__ float sw[81];
    if (threadIdx.x < 81) sw[threadIdx.x] = cw[threadIdx.x];
    __syncthreads();
    int idx = blockIdx.x * blockDim.x + threadIdx.x;
    if (idx >= 12 * NPIX) return;
    int w = idx % 384;
    int h = (idx / 384) % 384;
    int p = idx / NPIX;            // p = b*3 + co
    int co = p % 3, b = p / 3;
    float acc = 0.0f;
    #pragma unroll
    for (int cin = 0; cin < 3; cin++) {
        const float* xp = x + (size_t)(b*3 + cin)*NPIX;
        #pragma unroll
        for (int kh = 0; kh < 3; kh++) {
            int hh = h + kh - 1;
            if (hh < 0 || hh >= 384) continue;
            #pragma unroll
            for (int kw = 0; kw < 3; kw++) {
                int ww = w + kw - 1;
                if (ww < 0 || ww >= 384) continue;
                acc += xp[(size_t)hh*384 + ww] * sw[((co*3 + cin)*3 + kh)*3 + kw];
            }
        }
    }
    g_XSP[idx] = acc;
}

// ---------------- launch ----------------
extern "C" void kernel_launch(void* const* d_in, const int* in_sizes, int n_in,
                              void* d_out, int out_size) {
    const float* x      = (const float*)d_in[0];
    const float* theta  = (const float*)d_in[1];
    const float* sigma  = (const float*)d_in[2];
    const float* f0     = (const float*)d_in[3];
    const float* theta0 = (const float*)d_in[4];
    const float* w1     = (const float*)d_in[5];
    const float* b1v    = (const float*)d_in[6];
    const float* w2     = (const float*)d_in[7];
    const float* b2v    = (const float*)d_in[8];
    const float* convw  = (const float*)d_in[9];
    const float* mixing = (const float*)d_in[10];
    const float* band   = (const float*)d_in[11];
    float* out = (float*)d_out;

    k_twiddle<<<1, 384>>>();
    k_fwd_rows<<<12 * 384 / 4, 768>>>(x);
    k_fwd_cols<<<48 * 12, 256>>>();
    k_attn<<<NPIX / 256, 256>>>(theta, sigma, f0, theta0, w1, b1v, w2, b2v);
    k_conv<<<(12 * NPIX + 255) / 256, 256>>>(x, convw);
    k_ifft_rows<<<36 * 192, 192>>>(band);
    k_ifft_cols_combine<<<48 * 36, 256>>>(band, mixing, out);
}

// round 4
// speedup vs baseline: 1.7938x; 1.0209x over previous
#include <cuda_runtime.h>
#include <math.h>

#define NPIX (384*384)   // 147456
#define TC 8             // columns per tile in column-FFT kernels

typedef unsigned long long ull;

__device__ __forceinline__ float2 cmul(float2 a, float2 b) {
    return make_float2(a.x*b.x - a.y*b.y, a.x*b.y + a.y*b.x);
}

// packed f32x2 ops (sm_100+; FFMA2 path, PTX-only)
#define FMA_F32X2(d, a, b, c) \
    asm("fma.rn.f32x2 %0, %1, %2, %3;" : "=l"(d) : "l"(a), "l"(b), "l"(c))
#define PACK2F(out, lo, hi) \
    asm("mov.b64 %0, {%1, %2};" : "=l"(out) : "r"(__float_as_uint(lo)), "r"(__float_as_uint(hi)))
__device__ __forceinline__ void unpack2f(ull v, float& lo, float& hi) {
    unsigned a, b;
    asm("mov.b64 {%0, %1}, %2;" : "=r"(a), "=r"(b) : "l"(v));
    lo = __uint_as_float(a); hi = __uint_as_float(b);
}

// ---------------- scratch (static device globals; no allocation) ----------------
__device__ float2 g_Tmp[36 * NPIX];   // ping scratch (forward uses 12 planes, inverse 36)
__device__ float2 g_Y  [12 * NPIX];   // x_freq_shift (shifted + relabeled): [b',c',h',w']
__device__ float2 g_Att[ 4 * NPIX];   // attended [b,h,w] complex
__device__ float  g_XSP[12 * NPIX];   // spatial conv [b,co,h,w]

// fill twiddle table in shared: tw[k] = e^{-2pi i k/384}
__device__ __forceinline__ void fill_tw(float2* tw, int tid, int nthreads) {
    for (int i = tid; i < 384; i += nthreads) {
        float s, c;
        sincospif(2.0f * (float)i / 384.0f, &s, &c);
        tw[i] = make_float2(c, -s);
    }
}

// ---------------- 384-pt FFT on one row in shared (192 threads per row) ----------------
template<int DIR>
__device__ void fft384_row(float2* sa, const float2* tw, int tid) {
    __syncthreads();
    int idx0 = tid, idx1 = tid + 192;
    int j0 = idx0 & 127, n20 = idx0 >> 7;
    int j1 = idx1 & 127, n21 = idx1 >> 7;
    int r0 = __brev((unsigned)j0) >> 25;
    int r1 = __brev((unsigned)j1) >> 25;
    float2 v0 = sa[3*r0 + n20];
    float2 v1 = sa[3*r1 + n21];
    __syncthreads();
    sa[idx0] = v0; sa[idx1] = v1;
    __syncthreads();

    int n2 = tid / 64;
    int tb = tid % 64;
    int m = 192;
    #pragma unroll
    for (int len = 2; len <= 128; len <<= 1, m >>= 1) {
        int half = len >> 1;
        int blk  = tb / half;
        int j    = tb - blk*half;
        int base = n2*128 + blk*len + j;
        float2 w = tw[j * m];
        if (DIR > 0) w.y = -w.y;
        float2 u = sa[base];
        float2 t = cmul(sa[base + half], w);
        sa[base]        = make_float2(u.x + t.x, u.y + t.y);
        sa[base + half] = make_float2(u.x - t.x, u.y - t.y);
        __syncthreads();
    }

    if (tid < 128) {
        int k1 = tid;
        float2 t0 = sa[k1];
        float2 t1 = sa[128 + k1];
        float2 t2 = sa[256 + k1];
        float2 w1 = tw[k1], w2 = tw[2*k1];
        if (DIR > 0) { w1.y = -w1.y; w2.y = -w2.y; }
        t1 = cmul(t1, w1);
        t2 = cmul(t2, w2);
        const float s3 = DIR * 0.86602540378443864676f;
        float2 w3  = make_float2(-0.5f,  s3);
        float2 w3b = make_float2(-0.5f, -s3);
        float2 a1 = cmul(t1, w3),  a2 = cmul(t2, w3b);
        float2 b1 = cmul(t1, w3b), b2 = cmul(t2, w3);
        sa[k1]       = make_float2(t0.x + t1.x + t2.x, t0.y + t1.y + t2.y);
        sa[128 + k1] = make_float2(t0.x + a1.x + a2.x, t0.y + a1.y + a2.y);
        sa[256 + k1] = make_float2(t0.x + b1.x + b2.x, t0.y + b1.y + b2.y);
    }
    __syncthreads();
}

// ---------------- 384-pt FFT over TC=8 columns in shared (256 threads) ----------------
template<int DIR>
__device__ void fft384_cols8(float2* sa, const float2* tw, int tid) {
    int m = 192;
    #pragma unroll
    for (int len = 2; len <= 128; len <<= 1, m >>= 1) {
        int half = len >> 1;
        #pragma unroll
        for (int it = 0; it < 6; it++) {
            int idx = tid + it*256;
            int cc = idx & 7, t = idx >> 3;
            int n2 = t >> 6, tb = t & 63;
            int blk = tb / half;
            int j   = tb - blk*half;
            int b0  = (n2*128 + blk*len + j)*8 + cc;
            float2 w = tw[j * m];
            if (DIR > 0) w.y = -w.y;
            float2 u = sa[b0];
            float2 t2 = cmul(sa[b0 + half*8], w);
            sa[b0]          = make_float2(u.x + t2.x, u.y + t2.y);
            sa[b0 + half*8] = make_float2(u.x - t2.x, u.y - t2.y);
        }
        __syncthreads();
    }
    #pragma unroll
    for (int it = 0; it < 4; it++) {
        int idx = tid + it*256;
        int cc = idx & 7, k1 = idx >> 3;
        float2 t0 = sa[k1*8 + cc];
        float2 t1 = sa[(128 + k1)*8 + cc];
        float2 t2 = sa[(256 + k1)*8 + cc];
        float2 w1 = tw[k1], w2 = tw[2*k1];
        if (DIR > 0) { w1.y = -w1.y; w2.y = -w2.y; }
        t1 = cmul(t1, w1);
        t2 = cmul(t2, w2);
        const float s3 = DIR * 0.86602540378443864676f;
        float2 w3  = make_float2(-0.5f,  s3);
        float2 w3b = make_float2(-0.5f, -s3);
        float2 a1 = cmul(t1, w3),  a2 = cmul(t2, w3b);
        float2 b1 = cmul(t1, w3b), b2 = cmul(t2, w3);
        sa[k1*8 + cc]         = make_float2(t0.x + t1.x + t2.x, t0.y + t1.y + t2.y);
        sa[(128 + k1)*8 + cc] = make_float2(t0.x + a1.x + a2.x, t0.y + a1.y + a2.y);
        sa[(256 + k1)*8 + cc] = make_float2(t0.x + b1.x + b2.x, t0.y + b1.y + b2.y);
    }
    __syncthreads();
}

// ---------------- forward FFT, rows (4 rows per block) ----------------
__global__ void k_fwd_rows(const float* __restrict__ x) {
    __shared__ float2 sa4[4][384];
    __shared__ float2 tw[384];
    int tid = threadIdx.x;                     // 768
    int rg  = tid / 192;
    int rt  = tid % 192;
    fill_tw(tw, tid, 768);
    int gr = blockIdx.x * 4 + rg;
    int p = gr / 384, h = gr % 384;
    float2* sa = sa4[rg];
    const float* row = x + (size_t)p*NPIX + (size_t)h*384;
    sa[rt]       = make_float2(row[rt],       0.0f);
    sa[rt + 192] = make_float2(row[rt + 192], 0.0f);
    fft384_row<-1>(sa, tw, rt);
    float2* o = g_Tmp + (size_t)p*NPIX + (size_t)h*384;
    o[rt] = sa[rt]; o[rt + 192] = sa[rt + 192];
}

// ---------------- forward FFT, cols (tiled) + fftshift + batch/channel relabel ----------------
__global__ void k_fwd_cols() {
    __shared__ float2 sa[384 * TC];
    __shared__ float2 tw[384];
    int tile = blockIdx.x % 48, p = blockIdx.x / 48;
    int b = p / 3, c = p % 3;
    int w0 = tile * TC;
    int tid = threadIdx.x;                     // 256
    fill_tw(tw, tid, 256);
    for (int i = tid; i < 384*TC; i += 256) {
        int cc = i & 7, t = i >> 3;
        int j = t & 127, n2 = t >> 7;
        int r = __brev((unsigned)j) >> 25;
        int hsrc = 3*r + n2;
        sa[i] = g_Tmp[(size_t)p*NPIX + (size_t)hsrc*384 + w0 + cc];
    }
    __syncthreads();
    fft384_cols8<-1>(sa, tw, tid);
    int pp = ((b + 2) & 3) * 3 + ((c + 1) % 3);
    int wp0 = (w0 + 192) % 384;
    for (int i = tid; i < 384*TC; i += 256) {
        int cc = i & 7, h = i >> 3;
        int hp = (h + 192) % 384;
        g_Y[(size_t)pp*NPIX + (size_t)hp*384 + wp0 + cc] = sa[i];
    }
}

// ---------------- fused attention: f32x2-packed MLP over batch pairs ----------------
__global__ void k_attn(const float* __restrict__ theta, const float* __restrict__ sigma,
                       const float* __restrict__ f0,    const float* __restrict__ theta0,
                       const float* __restrict__ w1,    const float* __restrict__ b1v,
                       const float* __restrict__ w2,    const float* __restrict__ b2v) {
    __shared__ float4 sW1B[64];         // {w1[j][0..2], b1[j]}
    __shared__ ull    sW2D[64*10];      // per j: 9 duplicate-packed w2 (+pad); 80B rows, 16B-aligned
    __shared__ float  sB2[9];
    __shared__ float  sLF0[27], sI2LS[27], sTH[27], sI2T0[27];
    int tid = threadIdx.x;  // 256
    if (tid < 64) {
        sW1B[tid] = make_float4(w1[tid*3], w1[tid*3+1], w1[tid*3+2], b1v[tid]);
        #pragma unroll
        for (int o = 0; o < 9; o++) {
            unsigned u = __float_as_uint(w2[o*64 + tid]);
            sW2D[tid*10 + o] = (ull)u | ((ull)u << 32);
        }
        sW2D[tid*10 + 9] = 0;
    }
    if (tid < 9)  sB2[tid] = b2v[tid];
    if (tid < 27) {
        sLF0[tid] = logf(f0[tid]);
        float ls = logf(sigma[tid]);
        sI2LS[tid] = 1.0f / (2.0f * ls * ls);
        sTH[tid]   = theta[tid];
        float t0 = theta0[tid];
        sI2T0[tid] = 1.0f / (2.0f * t0 * t0);
    }
    __syncthreads();

    int px = blockIdx.x * 256 + tid;
    if (px >= NPIX) return;

    // phase 1: magnitudes for all 4 batches
    float mag[12];
    #pragma unroll
    for (int b = 0; b < 4; b++)
        #pragma unroll
        for (int d = 0; d < 3; d++) {
            float2 yv = g_Y[(size_t)(b*3 + d)*NPIX + px];
            mag[b*3 + d] = sqrtf(yv.x*yv.x + yv.y*yv.y);
        }

    // phase 2: MLP, batches packed (0,1) and (2,3) into f32x2 lanes
    ull lgp0[9], lgp1[9];
    #pragma unroll
    for (int o = 0; o < 9; o++) {
        unsigned u = __float_as_uint(sB2[o]);
        lgp0[o] = (ull)u | ((ull)u << 32);
        lgp1[o] = lgp0[o];
    }
    for (int j = 0; j < 64; j++) {
        float4 wb = sW1B[j];
        float h0 = fmaxf(fmaf(wb.x, mag[0], fmaf(wb.y, mag[1],  fmaf(wb.z, mag[2],  wb.w))), 0.0f);
        float h1 = fmaxf(fmaf(wb.x, mag[3], fmaf(wb.y, mag[4],  fmaf(wb.z, mag[5],  wb.w))), 0.0f);
        float h2 = fmaxf(fmaf(wb.x, mag[6], fmaf(wb.y, mag[7],  fmaf(wb.z, mag[8],  wb.w))), 0.0f);
        float h3 = fmaxf(fmaf(wb.x, mag[9], fmaf(wb.y, mag[10], fmaf(wb.z, mag[11], wb.w))), 0.0f);
        ull hp0, hp1;
        PACK2F(hp0, h0, h1);
        PACK2F(hp1, h2, h3);
        const ull* wrow = sW2D + j*10;
        ulonglong2 wA = ((const ulonglong2*)wrow)[0];
        ulonglong2 wB = ((const ulonglong2*)wrow)[1];
        ulonglong2 wC = ((const ulonglong2*)wrow)[2];
        ulonglong2 wD = ((const ulonglong2*)wrow)[3];
        ull        w8 = wrow[8];
        FMA_F32X2(lgp0[0], hp0, wA.x, lgp0[0]);  FMA_F32X2(lgp1[0], hp1, wA.x, lgp1[0]);
        FMA_F32X2(lgp0[1], hp0, wA.y, lgp0[1]);  FMA_F32X2(lgp1[1], hp1, wA.y, lgp1[1]);
        FMA_F32X2(lgp0[2], hp0, wB.x, lgp0[2]);  FMA_F32X2(lgp1[2], hp1, wB.x, lgp1[2]);
        FMA_F32X2(lgp0[3], hp0, wB.y, lgp0[3]);  FMA_F32X2(lgp1[3], hp1, wB.y, lgp1[3]);
        FMA_F32X2(lgp0[4], hp0, wC.x, lgp0[4]);  FMA_F32X2(lgp1[4], hp1, wC.x, lgp1[4]);
        FMA_F32X2(lgp0[5], hp0, wC.y, lgp0[5]);  FMA_F32X2(lgp1[5], hp1, wC.y, lgp1[5]);
        FMA_F32X2(lgp0[6], hp0, wD.x, lgp0[6]);  FMA_F32X2(lgp1[6], hp1, wD.x, lgp1[6]);
        FMA_F32X2(lgp0[7], hp0, wD.y, lgp0[7]);  FMA_F32X2(lgp1[7], hp1, wD.y, lgp1[7]);
        FMA_F32X2(lgp0[8], hp0, w8,   lgp0[8]);  FMA_F32X2(lgp1[8], hp1, w8,   lgp1[8]);
    }
    float lg[36];
    #pragma unroll
    for (int o = 0; o < 9; o++) {
        unpack2f(lgp0[o], lg[0*9 + o], lg[1*9 + o]);
        unpack2f(lgp1[o], lg[2*9 + o], lg[3*9 + o]);
    }

    // phase 3: log-Gabor filters (geometry only)
    int h = px / 384, w = px % 384;
    float yy = -1.0f + 2.0f * (float)h / 383.0f;
    float xx = -1.0f + 2.0f * (float)w / 383.0f;
    float r   = sqrtf(xx*xx + yy*yy + 1e-6f);
    float phi = atan2f(yy, xx);
    float filt[27];
    #pragma unroll
    for (int i = 0; i < 27; i++) {
        float L  = logf(r - sLF0[i]);
        float dp = phi - sTH[i];
        filt[i] = expf(-(L*L*sI2LS[i] + dp*dp*sI2T0[i]));
    }

    // phase 4: softmax + weighted spectrum, per batch
    #pragma unroll
    for (int b = 0; b < 4; b++) {
        float mx = lg[b*9];
        #pragma unroll
        for (int o = 1; o < 9; o++) mx = fmaxf(mx, lg[b*9 + o]);
        float ex[9]; float se = 0.0f;
        #pragma unroll
        for (int o = 0; o < 9; o++) { ex[o] = expf(lg[b*9 + o] - mx); se += ex[o]; }
        float inv = 1.0f / se;

        float2 acc = make_float2(0.0f, 0.0f);
        #pragma unroll
        for (int d = 0; d < 3; d++) {
            float wg = 0.0f;
            #pragma unroll
            for (int o = 0; o < 9; o++) wg += ex[o] * filt[o*3 + d];
            wg *= inv;
            float2 yv = g_Y[(size_t)(b*3 + d)*NPIX + px];
            acc.x += yv.x * wg;
            acc.y += yv.y * wg;
        }
        g_Att[(size_t)b*NPIX + px] = acc;
    }
}

// ---------------- inverse FFT rows of ifftshift(mask * attended) ----------------
__global__ void k_ifft_rows(const float* __restrict__ band) {
    __shared__ float2 sa[384];
    __shared__ float2 tw[384];
    int bh = blockIdx.x;
    int h = bh % 192, q = bh / 192;
    int ci = q % 3, b2 = (q / 3) & 3, co = q / 12;
    int cos_ = (co + 1) % 3, bs = (b2 + 2) & 3, cis = (ci + 1) % 3;
    int bi = (cos_*3 + cis) * 2;
    int si = (int)floorf((band[bi]     + 1.0f) / 2.0f * 384.0f);
    int ei = (int)floorf((band[bi + 1] + 1.0f) / 2.0f * 384.0f);
    int hs = h + 192;
    if (!((si < ei) && (hs >= si) && (hs < ei))) return;   // zero row: skip entirely

    int tid = threadIdx.x;
    fill_tw(tw, tid, 192);
    const float2* arow = g_Att + (size_t)bs*NPIX + (size_t)hs*384;
    #pragma unroll
    for (int k = 0; k < 2; k++) {
        int w  = tid + k*192;
        int ws = (w + 192) % 384;
        bool on = (ws >= si) && (ws < ei);
        sa[w] = on ? arow[ws] : make_float2(0.0f, 0.0f);
    }
    fft384_row<1>(sa, tw, tid);
    float2* o = g_Tmp + (size_t)q*NPIX + (size_t)h*384;
    o[tid] = sa[tid]; o[tid + 192] = sa[tid + 192];
}

// ---------------- inverse FFT cols (tiled) fused with mix + b1-broadcast write ----------------
__global__ void k_ifft_cols_combine(const float* __restrict__ band,
                                    const float* __restrict__ mixing,
                                    float* __restrict__ out) {
    __shared__ float2 sa[384 * TC];
    __shared__ float2 tw[384];
    int tile = blockIdx.x % 48, q = blockIdx.x / 48;
    int ci = q % 3, b2 = (q / 3) & 3, co = q / 12;
    int cos_ = (co + 1) % 3, cis = (ci + 1) % 3;
    int bi = (cos_*3 + cis) * 2;
    int si = (int)floorf((band[bi]     + 1.0f) / 2.0f * 384.0f);
    int ei = (int)floorf((band[bi + 1] + 1.0f) / 2.0f * 384.0f);
    int h0 = si - 192, h1e = ei - 192;
    int tid = threadIdx.x;                     // 256
    int w0 = tile * TC;
    float mix = mixing[0];
    const float* xsp = g_XSP + (size_t)(b2*3 + ci)*NPIX;
    const size_t NIN = (size_t)36 * NPIX;

    if (si >= ei) {                            // fully-masked plane: x_filtered = 0
        for (int i = tid; i < 384*TC; i += 256) {
            int cc = i & 7, h = i >> 3;
            size_t px = (size_t)h*384 + w0 + cc;
            float val = (1.0f - mix) * xsp[px];
            size_t o = (size_t)q*NPIX + px;
            #pragma unroll
            for (int b1 = 0; b1 < 4; b1++) out[(size_t)b1*NIN + o] = val;
        }
        return;
    }

    fill_tw(tw, tid, 256);
    for (int i = tid; i < 384*TC; i += 256) {
        int cc = i & 7, t = i >> 3;
        int j = t & 127, n2 = t >> 7;
        int r = __brev((unsigned)j) >> 25;
        int hsrc = 3*r + n2;
        float2 v = make_float2(0.0f, 0.0f);
        if (hsrc >= h0 && hsrc < h1e)
            v = g_Tmp[(size_t)q*NPIX + (size_t)hsrc*384 + w0 + cc];
        sa[i] = v;
    }
    __syncthreads();
    fft384_cols8<1>(sa, tw, tid);

    const float sc = 1.0f / (384.0f * 384.0f);
    for (int i = tid; i < 384*TC; i += 256) {
        int cc = i & 7, h = i >> 3;
        size_t px = (size_t)h*384 + w0 + cc;
        float val = mix * (sa[i].x * sc) + (1.0f - mix) * xsp[px];
        size_t o = (size_t)q*NPIX + px;
        #pragma unroll
        for (int b1 = 0; b1 < 4; b1++) out[(size_t)b1*NIN + o] = val;
    }
}

// ---------------- 3x3 spatial conv (cross-correlation, pad 1) ----------------
__global__ void k_conv(const float* __restrict__ x, const float* __restrict__ cw) {
    __shared__ float sw[81];
    if (threadIdx.x < 81) sw[threadIdx.x] = cw[threadIdx.x];
    __syncthreads();
    int idx = blockIdx.x * blockDim.x + threadIdx.x;
    if (idx >= 12 * NPIX) return;
    int w = idx % 384;
    int h = (idx / 384) % 384;
    int p = idx / NPIX;            // p = b*3 + co
    int co = p % 3, b = p / 3;
    float acc = 0.0f;
    #pragma unroll
    for (int cin = 0; cin < 3; cin++) {
        const float* xp = x + (size_t)(b*3 + cin)*NPIX;
        #pragma unroll
        for (int kh = 0; kh < 3; kh++) {
            int hh = h + kh - 1;
            if (hh < 0 || hh >= 384) continue;
            #pragma unroll
            for (int kw = 0; kw < 3; kw++) {
                int ww = w + kw - 1;
                if (ww < 0 || ww >= 384) continue;
                acc += xp[(size_t)hh*384 + ww] * sw[((co*3 + cin)*3 + kh)*3 + kw];
            }
        }
    }
    g_XSP[idx] = acc;
}

// ---------------- launch ----------------
extern "C" void kernel_launch(void* const* d_in, const int* in_sizes, int n_in,
                              void* d_out, int out_size) {
    const float* x      = (const float*)d_in[0];
    const float* theta  = (const float*)d_in[1];
    const float* sigma  = (const float*)d_in[2];
    const float* f0     = (const float*)d_in[3];
    const float* theta0 = (const float*)d_in[4];
    const float* w1     = (const float*)d_in[5];
    const float* b1v    = (const float*)d_in[6];
    const float* w2     = (const float*)d_in[7];
    const float* b2v    = (const float*)d_in[8];
    const float* convw  = (const float*)d_in[9];
    const float* mixing = (const float*)d_in[10];
    const float* band   = (const float*)d_in[11];
    float* out = (float*)d_out;

    k_fwd_rows<<<12 * 384 / 4, 768>>>(x);
    k_fwd_cols<<<48 * 12, 256>>>();
    k_attn<<<NPIX / 256, 256>>>(theta, sigma, f0, theta0, w1, b1v, w2, b2v);
    k_conv<<<(12 * NPIX + 255) / 256, 256>>>(x, convw);
    k_ifft_rows<<<36 * 192, 192>>>(band);
    k_ifft_cols_combine<<<48 * 36, 256>>>(band, mixing, out);
}

// round 6
// speedup vs baseline: 1.9265x; 1.0740x over previous
#include <cuda_runtime.h>
#include <math.h>

#define NPIX (384*384)   // 147456
#define TC 8             // columns per tile in column-FFT kernels

typedef unsigned long long ull;

__device__ __forceinline__ float2 cmul(float2 a, float2 b) {
    return make_float2(a.x*b.x - a.y*b.y, a.x*b.y + a.y*b.x);
}

// packed f32x2 ops (sm_100+; FFMA2 path, PTX-only)
#define FMA_F32X2(d, a, b, c) \
    asm("fma.rn.f32x2 %0, %1, %2, %3;" : "=l"(d) : "l"(a), "l"(b), "l"(c))
#define PACK2F(out, lo, hi) \
    asm("mov.b64 %0, {%1, %2};" : "=l"(out) : "r"(__float_as_uint(lo)), "r"(__float_as_uint(hi)))
__device__ __forceinline__ void unpack2f(ull v, float& lo, float& hi) {
    unsigned a, b;
    asm("mov.b64 {%0, %1}, %2;" : "=r"(a), "=r"(b) : "l"(v));
    lo = __uint_as_float(a); hi = __uint_as_float(b);
}

// ---------------- scratch (static device globals; no allocation) ----------------
__device__ float2 g_Tmp[36 * NPIX];   // ping scratch (forward uses 12 planes, inverse 36)
__device__ float2 g_Y  [12 * NPIX];   // x_freq_shift (shifted + relabeled): [b',c',h',w']
__device__ float2 g_Att[ 4 * NPIX];   // attended [b,h,w] complex
__device__ float  g_XSP[12 * NPIX];   // spatial conv [b,co,h,w]

// fill twiddle table in shared: tw[k] = e^{-2pi i k/384}
__device__ __forceinline__ void fill_tw(float2* tw, int tid, int nthreads) {
    for (int i = tid; i < 384; i += nthreads) {
        float s, c;
        sincospif(2.0f * (float)i / 384.0f, &s, &c);
        tw[i] = make_float2(c, -s);
    }
}

// ---------------- 384-pt FFT on one row in shared (192 threads per row) ----------------
template<int DIR>
__device__ void fft384_row(float2* sa, const float2* tw, int tid) {
    __syncthreads();
    int idx0 = tid, idx1 = tid + 192;
    int j0 = idx0 & 127, n20 = idx0 >> 7;
    int j1 = idx1 & 127, n21 = idx1 >> 7;
    int r0 = __brev((unsigned)j0) >> 25;
    int r1 = __brev((unsigned)j1) >> 25;
    float2 v0 = sa[3*r0 + n20];
    float2 v1 = sa[3*r1 + n21];
    __syncthreads();
    sa[idx0] = v0; sa[idx1] = v1;
    __syncthreads();

    int n2 = tid / 64;
    int tb = tid % 64;
    int m = 192;
    #pragma unroll
    for (int len = 2; len <= 128; len <<= 1, m >>= 1) {
        int half = len >> 1;
        int blk  = tb / half;
        int j    = tb - blk*half;
        int base = n2*128 + blk*len + j;
        float2 w = tw[j * m];
        if (DIR > 0) w.y = -w.y;
        float2 u = sa[base];
        float2 t = cmul(sa[base + half], w);
        sa[base]        = make_float2(u.x + t.x, u.y + t.y);
        sa[base + half] = make_float2(u.x - t.x, u.y - t.y);
        __syncthreads();
    }

    if (tid < 128) {
        int k1 = tid;
        float2 t0 = sa[k1];
        float2 t1 = sa[128 + k1];
        float2 t2 = sa[256 + k1];
        float2 w1 = tw[k1], w2 = tw[2*k1];
        if (DIR > 0) { w1.y = -w1.y; w2.y = -w2.y; }
        t1 = cmul(t1, w1);
        t2 = cmul(t2, w2);
        const float s3 = DIR * 0.86602540378443864676f;
        float2 w3  = make_float2(-0.5f,  s3);
        float2 w3b = make_float2(-0.5f, -s3);
        float2 a1 = cmul(t1, w3),  a2 = cmul(t2, w3b);
        float2 b1 = cmul(t1, w3b), b2 = cmul(t2, w3);
        sa[k1]       = make_float2(t0.x + t1.x + t2.x, t0.y + t1.y + t2.y);
        sa[128 + k1] = make_float2(t0.x + a1.x + a2.x, t0.y + a1.y + a2.y);
        sa[256 + k1] = make_float2(t0.x + b1.x + b2.x, t0.y + b1.y + b2.y);
    }
    __syncthreads();
}

// ---------------- 384-pt FFT over TC=8 columns in shared (256 threads) ----------------
template<int DIR>
__device__ void fft384_cols8(float2* sa, const float2* tw, int tid) {
    int m = 192;
    #pragma unroll
    for (int len = 2; len <= 128; len <<= 1, m >>= 1) {
        int half = len >> 1;
        #pragma unroll
        for (int it = 0; it < 6; it++) {
            int idx = tid + it*256;
            int cc = idx & 7, t = idx >> 3;
            int n2 = t >> 6, tb = t & 63;
            int blk = tb / half;
            int j   = tb - blk*half;
            int b0  = (n2*128 + blk*len + j)*8 + cc;
            float2 w = tw[j * m];
            if (DIR > 0) w.y = -w.y;
            float2 u = sa[b0];
            float2 t2 = cmul(sa[b0 + half*8], w);
            sa[b0]          = make_float2(u.x + t2.x, u.y + t2.y);
            sa[b0 + half*8] = make_float2(u.x - t2.x, u.y - t2.y);
        }
        __syncthreads();
    }
    #pragma unroll
    for (int it = 0; it < 4; it++) {
        int idx = tid + it*256;
        int cc = idx & 7, k1 = idx >> 3;
        float2 t0 = sa[k1*8 + cc];
        float2 t1 = sa[(128 + k1)*8 + cc];
        float2 t2 = sa[(256 + k1)*8 + cc];
        float2 w1 = tw[k1], w2 = tw[2*k1];
        if (DIR > 0) { w1.y = -w1.y; w2.y = -w2.y; }
        t1 = cmul(t1, w1);
        t2 = cmul(t2, w2);
        const float s3 = DIR * 0.86602540378443864676f;
        float2 w3  = make_float2(-0.5f,  s3);
        float2 w3b = make_float2(-0.5f, -s3);
        float2 a1 = cmul(t1, w3),  a2 = cmul(t2, w3b);
        float2 b1 = cmul(t1, w3b), b2 = cmul(t2, w3);
        sa[k1*8 + cc]         = make_float2(t0.x + t1.x + t2.x, t0.y + t1.y + t2.y);
        sa[(128 + k1)*8 + cc] = make_float2(t0.x + a1.x + a2.x, t0.y + a1.y + a2.y);
        sa[(256 + k1)*8 + cc] = make_float2(t0.x + b1.x + b2.x, t0.y + b1.y + b2.y);
    }
    __syncthreads();
}

// ---------------- forward FFT, rows (4 rows per block) ----------------
__global__ void k_fwd_rows(const float* __restrict__ x) {
    __shared__ float2 sa4[4][384];
    __shared__ float2 tw[384];
    int tid = threadIdx.x;                     // 768
    int rg  = tid / 192;
    int rt  = tid % 192;
    fill_tw(tw, tid, 768);
    int gr = blockIdx.x * 4 + rg;
    int p = gr / 384, h = gr % 384;
    float2* sa = sa4[rg];
    const float* row = x + (size_t)p*NPIX + (size_t)h*384;
    sa[rt]       = make_float2(row[rt],       0.0f);
    sa[rt + 192] = make_float2(row[rt + 192], 0.0f);
    fft384_row<-1>(sa, tw, rt);
    float2* o = g_Tmp + (size_t)p*NPIX + (size_t)h*384;
    o[rt] = sa[rt]; o[rt + 192] = sa[rt + 192];
}

// ---------------- forward FFT, cols (tiled) + fftshift + batch/channel relabel ----------------
__global__ void k_fwd_cols() {
    __shared__ float2 sa[384 * TC];
    __shared__ float2 tw[384];
    int tile = blockIdx.x % 48, p = blockIdx.x / 48;
    int b = p / 3, c = p % 3;
    int w0 = tile * TC;
    int tid = threadIdx.x;                     // 256
    fill_tw(tw, tid, 256);
    for (int i = tid; i < 384*TC; i += 256) {
        int cc = i & 7, t = i >> 3;
        int j = t & 127, n2 = t >> 7;
        int r = __brev((unsigned)j) >> 25;
        int hsrc = 3*r + n2;
        sa[i] = g_Tmp[(size_t)p*NPIX + (size_t)hsrc*384 + w0 + cc];
    }
    __syncthreads();
    fft384_cols8<-1>(sa, tw, tid);
    int pp = ((b + 2) & 3) * 3 + ((c + 1) % 3);
    int wp0 = (w0 + 192) % 384;
    for (int i = tid; i < 384*TC; i += 256) {
        int cc = i & 7, h = i >> 3;
        int hp = (h + 192) % 384;
        g_Y[(size_t)pp*NPIX + (size_t)hp*384 + wp0 + cc] = sa[i];
    }
}

// ---------------- fused attention: one batch-pair per block (grid.y), f32x2 MLP ----------------
__global__ void k_attn(const float* __restrict__ theta, const float* __restrict__ sigma,
                       const float* __restrict__ f0,    const float* __restrict__ theta0,
                       const float* __restrict__ w1,    const float* __restrict__ b1v,
                       const float* __restrict__ w2,    const float* __restrict__ b2v) {
    __shared__ float4 sW1B[64];         // {w1[j][0..2], b1[j]}
    __shared__ ull    sW2D[64*10];      // per j: 9 duplicate-packed w2 (+pad); 80B rows
    __shared__ float  sB2[9];
    __shared__ float  sLF0[27], sI2LS[27], sTH[27], sI2T0[27];
    int tid = threadIdx.x;  // 256
    if (tid < 64) {
        sW1B[tid] = make_float4(w1[tid*3], w1[tid*3+1], w1[tid*3+2], b1v[tid]);
        #pragma unroll
        for (int o = 0; o < 9; o++) {
            unsigned u = __float_as_uint(w2[o*64 + tid]);
            sW2D[tid*10 + o] = (ull)u | ((ull)u << 32);
        }
        sW2D[tid*10 + 9] = 0;
    }
    if (tid < 9)  sB2[tid] = b2v[tid];
    if (tid < 27) {
        sLF0[tid] = logf(f0[tid]);
        float ls = logf(sigma[tid]);
        sI2LS[tid] = 1.0f / (2.0f * ls * ls);
        sTH[tid]   = theta[tid];
        float t0 = theta0[tid];
        sI2T0[tid] = 1.0f / (2.0f * t0 * t0);
    }
    __syncthreads();

    int px = blockIdx.x * 256 + tid;
    if (px >= NPIX) return;
    int bp = blockIdx.y;                // batch pair: batches 2*bp, 2*bp+1

    // phase 1: magnitudes for the 2 batches
    float mag[6];
    #pragma unroll
    for (int bb = 0; bb < 2; bb++)
        #pragma unroll
        for (int d = 0; d < 3; d++) {
            float2 yv = g_Y[(size_t)((2*bp + bb)*3 + d)*NPIX + px];
            mag[bb*3 + d] = sqrtf(yv.x*yv.x + yv.y*yv.y);
        }

    // phase 2: MLP, both batches packed into f32x2 lanes
    ull lgp[9];
    #pragma unroll
    for (int o = 0; o < 9; o++) {
        unsigned u = __float_as_uint(sB2[o]);
        lgp[o] = (ull)u | ((ull)u << 32);
    }
    for (int j = 0; j < 64; j++) {
        float4 wb = sW1B[j];
        float h0 = fmaxf(fmaf(wb.x, mag[0], fmaf(wb.y, mag[1], fmaf(wb.z, mag[2], wb.w))), 0.0f);
        float h1 = fmaxf(fmaf(wb.x, mag[3], fmaf(wb.y, mag[4], fmaf(wb.z, mag[5], wb.w))), 0.0f);
        ull hp;
        PACK2F(hp, h0, h1);
        const ull* wrow = sW2D + j*10;
        ulonglong2 wA = ((const ulonglong2*)wrow)[0];
        ulonglong2 wB = ((const ulonglong2*)wrow)[1];
        ulonglong2 wC = ((const ulonglong2*)wrow)[2];
        ulonglong2 wD = ((const ulonglong2*)wrow)[3];
        ull        w8 = wrow[8];
        FMA_F32X2(lgp[0], hp, wA.x, lgp[0]);
        FMA_F32X2(lgp[1], hp, wA.y, lgp[1]);
        FMA_F32X2(lgp[2], hp, wB.x, lgp[2]);
        FMA_F32X2(lgp[3], hp, wB.y, lgp[3]);
        FMA_F32X2(lgp[4], hp, wC.x, lgp[4]);
        FMA_F32X2(lgp[5], hp, wC.y, lgp[5]);
        FMA_F32X2(lgp[6], hp, wD.x, lgp[6]);
        FMA_F32X2(lgp[7], hp, wD.y, lgp[7]);
        FMA_F32X2(lgp[8], hp, w8,   lgp[8]);
    }

    // geometry (shared by both batches)
    int h = px / 384, w = px % 384;
    float yy = -1.0f + 2.0f * (float)h / 383.0f;
    float xx = -1.0f + 2.0f * (float)w / 383.0f;
    float r   = sqrtf(xx*xx + yy*yy + 1e-6f);
    float phi = atan2f(yy, xx);

    // phase 3+4: per batch: softmax, then on-the-fly Gabor weighting
    #pragma unroll
    for (int bb = 0; bb < 2; bb++) {
        float lg[9];
        #pragma unroll
        for (int o = 0; o < 9; o++) {
            float lo_, hi_;
            unpack2f(lgp[o], lo_, hi_);
            lg[o] = bb ? hi_ : lo_;
        }
        float mx = lg[0];
        #pragma unroll
        for (int o = 1; o < 9; o++) mx = fmaxf(mx, lg[o]);
        float ex[9]; float se = 0.0f;
        #pragma unroll
        for (int o = 0; o < 9; o++) { ex[o] = expf(lg[o] - mx); se += ex[o]; }
        float inv = 1.0f / se;

        float wg[3] = {0.0f, 0.0f, 0.0f};
        #pragma unroll
        for (int o = 0; o < 9; o++) {
            #pragma unroll
            for (int d = 0; d < 3; d++) {
                int i = o*3 + d;
                float L  = logf(r - sLF0[i]);
                float dp = phi - sTH[i];
                float ft = expf(-(L*L*sI2LS[i] + dp*dp*sI2T0[i]));
                wg[d] = fmaf(ex[o], ft, wg[d]);
            }
        }
        int b = 2*bp + bb;
        float2 acc = make_float2(0.0f, 0.0f);
        #pragma unroll
        for (int d = 0; d < 3; d++) {
            float2 yv = g_Y[(size_t)(b*3 + d)*NPIX + px];
            float wgt = wg[d] * inv;
            acc.x = fmaf(yv.x, wgt, acc.x);
            acc.y = fmaf(yv.y, wgt, acc.y);
        }
        g_Att[(size_t)b*NPIX + px] = acc;
    }
}

// ---------------- inverse FFT rows of ifftshift(mask * attended) ----------------
__global__ void k_ifft_rows(const float* __restrict__ band) {
    __shared__ float2 sa[384];
    __shared__ float2 tw[384];
    int bh = blockIdx.x;
    int h = bh % 192, q = bh / 192;
    int ci = q % 3, b2 = (q / 3) & 3, co = q / 12;
    int cos_ = (co + 1) % 3, bs = (b2 + 2) & 3, cis = (ci + 1) % 3;
    int bi = (cos_*3 + cis) * 2;
    int si = (int)floorf((band[bi]     + 1.0f) / 2.0f * 384.0f);
    int ei = (int)floorf((band[bi + 1] + 1.0f) / 2.0f * 384.0f);
    int hs = h + 192;
    if (!((si < ei) && (hs >= si) && (hs < ei))) return;   // zero row: skip entirely

    int tid = threadIdx.x;
    fill_tw(tw, tid, 192);
    const float2* arow = g_Att + (size_t)bs*NPIX + (size_t)hs*384;
    #pragma unroll
    for (int k = 0; k < 2; k++) {
        int w  = tid + k*192;
        int ws = (w + 192) % 384;
        bool on = (ws >= si) && (ws < ei);
        sa[w] = on ? arow[ws] : make_float2(0.0f, 0.0f);
    }
    fft384_row<1>(sa, tw, tid);
    float2* o = g_Tmp + (size_t)q*NPIX + (size_t)h*384;
    o[tid] = sa[tid]; o[tid + 192] = sa[tid + 192];
}

// ---------------- inverse FFT cols (tiled) fused with mix + b1-broadcast write ----------------
__global__ void k_ifft_cols_combine(const float* __restrict__ band,
                                    const float* __restrict__ mixing,
                                    float* __restrict__ out) {
    __shared__ float2 sa[384 * TC];
    __shared__ float2 tw[384];
    int tile = blockIdx.x % 48, q = blockIdx.x / 48;
    int ci = q % 3, b2 = (q / 3) & 3, co = q / 12;
    int cos_ = (co + 1) % 3, cis = (ci + 1) % 3;
    int bi = (cos_*3 + cis) * 2;
    int si = (int)floorf((band[bi]     + 1.0f) / 2.0f * 384.0f);
    int ei = (int)floorf((band[bi + 1] + 1.0f) / 2.0f * 384.0f);
    int h0 = si - 192, h1e = ei - 192;
    int tid = threadIdx.x;                     // 256
    int w0 = tile * TC;
    float mix = mixing[0];
    const float* xsp = g_XSP + (size_t)(b2*3 + ci)*NPIX;
    const size_t NIN = (size_t)36 * NPIX;

    if (si >= ei) {                            // fully-masked plane: x_filtered = 0
        for (int i = tid; i < 384*TC; i += 256) {
            int cc = i & 7, h = i >> 3;
            size_t px = (size_t)h*384 + w0 + cc;
            float val = (1.0f - mix) * xsp[px];
            size_t o = (size_t)q*NPIX + px;
            #pragma unroll
            for (int b1 = 0; b1 < 4; b1++) out[(size_t)b1*NIN + o] = val;
        }
        return;
    }

    fill_tw(tw, tid, 256);
    for (int i = tid; i < 384*TC; i += 256) {
        int cc = i & 7, t = i >> 3;
        int j = t & 127, n2 = t >> 7;
        int r = __brev((unsigned)j) >> 25;
        int hsrc = 3*r + n2;
        float2 v = make_float2(0.0f, 0.0f);
        if (hsrc >= h0 && hsrc < h1e)
            v = g_Tmp[(size_t)q*NPIX + (size_t)hsrc*384 + w0 + cc];
        sa[i] = v;
    }
    __syncthreads();
    fft384_cols8<1>(sa, tw, tid);

    const float sc = 1.0f / (384.0f * 384.0f);
    for (int i = tid; i < 384*TC; i += 256) {
        int cc = i & 7, h = i >> 3;
        size_t px = (size_t)h*384 + w0 + cc;
        float val = mix * (sa[i].x * sc) + (1.0f - mix) * xsp[px];
        size_t o = (size_t)q*NPIX + px;
        #pragma unroll
        for (int b1 = 0; b1 < 4; b1++) out[(size_t)b1*NIN + o] = val;
    }
}

// ---------------- 3x3 spatial conv: shared-tiled, 3 outputs/thread ----------------
__global__ void k_conv(const float* __restrict__ x, const float* __restrict__ cw) {
    __shared__ float sx[3 * 10 * 36];   // 3 cin planes, 10 rows x 34 cols (36 stride)
    __shared__ float sw[81];
    int tid = threadIdx.x;              // 256
    if (tid < 81) sw[tid] = cw[tid];
    int bidx = blockIdx.x;              // 4 * 48 * 12 = 2304
    int twi = bidx % 12, thi = (bidx / 12) % 48, b = bidx / (12 * 48);
    int w0 = twi * 32, h0 = thi * 8;

    for (int i = tid; i < 3 * 340; i += 256) {
        int c = i / 340, rem = i % 340;
        int rr = rem / 34, cc = rem % 34;
        int hh = h0 + rr - 1, ww = w0 + cc - 1;
        float v = 0.0f;
        if (hh >= 0 && hh < 384 && ww >= 0 && ww < 384)
            v = x[(size_t)(b*3 + c)*NPIX + (size_t)hh*384 + ww];
        sx[c*360 + rr*36 + cc] = v;
    }
    __syncthreads();

    int lw = tid % 32, lh = tid / 32;   // 32 x 8 outputs
    float acc0 = 0.0f, acc1 = 0.0f, acc2 = 0.0f;
    #pragma unroll
    for (int c = 0; c < 3; c++) {
        #pragma unroll
        for (int kh = 0; kh < 3; kh++) {
            #pragma unroll
            for (int kw = 0; kw < 3; kw++) {
                float v = sx[c*360 + (lh + kh)*36 + (lw + kw)];
                int ki = c*9 + kh*3 + kw;
                acc0 = fmaf(v, sw[ki],      acc0);
                acc1 = fmaf(v, sw[27 + ki], acc1);
                acc2 = fmaf(v, sw[54 + ki], acc2);
            }
        }
    }
    size_t px = (size_t)(h0 + lh)*384 + (w0 + lw);
    g_XSP[(size_t)(b*3 + 0)*NPIX + px] = acc0;
    g_XSP[(size_t)(b*3 + 1)*NPIX + px] = acc1;
    g_XSP[(size_t)(b*3 + 2)*NPIX + px] = acc2;
}

// ---------------- launch ----------------
extern "C" void kernel_launch(void* const* d_in, const int* in_sizes, int n_in,
                              void* d_out, int out_size) {
    const float* x      = (const float*)d_in[0];
    const float* theta  = (const float*)d_in[1];
    const float* sigma  = (const float*)d_in[2];
    const float* f0     = (const float*)d_in[3];
    const float* theta0 = (const float*)d_in[4];
    const float* w1     = (const float*)d_in[5];
    const float* b1v    = (const float*)d_in[6];
    const float* w2     = (const float*)d_in[7];
    const float* b2v    = (const float*)d_in[8];
    const float* convw  = (const float*)d_in[9];
    const float* mixing = (const float*)d_in[10];
    const float* band   = (const float*)d_in[11];
    float* out = (float*)d_out;

    k_fwd_rows<<<12 * 384 / 4, 768>>>(x);
    k_fwd_cols<<<48 * 12, 256>>>();
    k_attn<<<dim3(NPIX / 256, 2), 256>>>(theta, sigma, f0, theta0, w1, b1v, w2, b2v);
    k_conv<<<4 * 48 * 12, 256>>>(x, convw);
    k_ifft_rows<<<36 * 192, 192>>>(band);
    k_ifft_cols_combine<<<48 * 36, 256>>>(band, mixing, out);
}

// round 7
// speedup vs baseline: 1.9303x; 1.0020x over previous
#include <cuda_runtime.h>
#include <math.h>

#define NPIX (384*384)   // 147456
#define TC 8             // columns per tile in column-FFT kernels

typedef unsigned long long ull;

__device__ __forceinline__ float2 cmul(float2 a, float2 b) {
    return make_float2(a.x*b.x - a.y*b.y, a.x*b.y + a.y*b.x);
}

// packed f32x2 ops (sm_100+; FFMA2 path, PTX-only)
#define FMA_F32X2(d, a, b, c) \
    asm("fma.rn.f32x2 %0, %1, %2, %3;" : "=l"(d) : "l"(a), "l"(b), "l"(c))
#define PACK2F(out, lo, hi) \
    asm("mov.b64 %0, {%1, %2};" : "=l"(out) : "r"(__float_as_uint(lo)), "r"(__float_as_uint(hi)))
__device__ __forceinline__ void unpack2f(ull v, float& lo, float& hi) {
    unsigned a, b;
    asm("mov.b64 {%0, %1}, %2;" : "=r"(a), "=r"(b) : "l"(v));
    lo = __uint_as_float(a); hi = __uint_as_float(b);
}

// ---------------- scratch (static device globals; no allocation) ----------------
__device__ float2 g_Tmp[36 * NPIX];   // ping scratch (forward uses 12 planes, inverse 36)
__device__ float2 g_Y  [12 * NPIX];   // x_freq_shift (shifted + relabeled): [b',c',h',w']
__device__ float2 g_Att[ 4 * NPIX];   // attended [b,h,w] complex
__device__ float  g_XSP[12 * NPIX];   // spatial conv [b,co,h,w]

// fill twiddle table in shared: tw[k] = e^{-2pi i k/384}
__device__ __forceinline__ void fill_tw(float2* tw, int tid, int nthreads) {
    for (int i = tid; i < 384; i += nthreads) {
        float s, c;
        sincospif(2.0f * (float)i / 384.0f, &s, &c);
        tw[i] = make_float2(c, -s);
    }
}

// ---------------- 384-pt FFT on one row in shared (192 threads per row) ----------------
template<int DIR>
__device__ void fft384_row(float2* sa, const float2* tw, int tid) {
    __syncthreads();
    int idx0 = tid, idx1 = tid + 192;
    int j0 = idx0 & 127, n20 = idx0 >> 7;
    int j1 = idx1 & 127, n21 = idx1 >> 7;
    int r0 = __brev((unsigned)j0) >> 25;
    int r1 = __brev((unsigned)j1) >> 25;
    float2 v0 = sa[3*r0 + n20];
    float2 v1 = sa[3*r1 + n21];
    __syncthreads();
    sa[idx0] = v0; sa[idx1] = v1;
    __syncthreads();

    int n2 = tid / 64;
    int tb = tid % 64;
    int m = 192;
    #pragma unroll
    for (int len = 2; len <= 128; len <<= 1, m >>= 1) {
        int half = len >> 1;
        int blk  = tb / half;
        int j    = tb - blk*half;
        int base = n2*128 + blk*len + j;
        float2 w = tw[j * m];
        if (DIR > 0) w.y = -w.y;
        float2 u = sa[base];
        float2 t = cmul(sa[base + half], w);
        sa[base]        = make_float2(u.x + t.x, u.y + t.y);
        sa[base + half] = make_float2(u.x - t.x, u.y - t.y);
        __syncthreads();
    }

    if (tid < 128) {
        int k1 = tid;
        float2 t0 = sa[k1];
        float2 t1 = sa[128 + k1];
        float2 t2 = sa[256 + k1];
        float2 w1 = tw[k1], w2 = tw[2*k1];
        if (DIR > 0) { w1.y = -w1.y; w2.y = -w2.y; }
        t1 = cmul(t1, w1);
        t2 = cmul(t2, w2);
        const float s3 = DIR * 0.86602540378443864676f;
        float2 w3  = make_float2(-0.5f,  s3);
        float2 w3b = make_float2(-0.5f, -s3);
        float2 a1 = cmul(t1, w3),  a2 = cmul(t2, w3b);
        float2 b1 = cmul(t1, w3b), b2 = cmul(t2, w3);
        sa[k1]       = make_float2(t0.x + t1.x + t2.x, t0.y + t1.y + t2.y);
        sa[128 + k1] = make_float2(t0.x + a1.x + a2.x, t0.y + a1.y + a2.y);
        sa[256 + k1] = make_float2(t0.x + b1.x + b2.x, t0.y + b1.y + b2.y);
    }
    __syncthreads();
}

// ---------------- 384-pt FFT over TC=8 columns in shared (256 threads) ----------------
template<int DIR>
__device__ void fft384_cols8(float2* sa, const float2* tw, int tid) {
    int m = 192;
    #pragma unroll
    for (int len = 2; len <= 128; len <<= 1, m >>= 1) {
        int half = len >> 1;
        #pragma unroll
        for (int it = 0; it < 6; it++) {
            int idx = tid + it*256;
            int cc = idx & 7, t = idx >> 3;
            int n2 = t >> 6, tb = t & 63;
            int blk = tb / half;
            int j   = tb - blk*half;
            int b0  = (n2*128 + blk*len + j)*8 + cc;
            float2 w = tw[j * m];
            if (DIR > 0) w.y = -w.y;
            float2 u = sa[b0];
            float2 t2 = cmul(sa[b0 + half*8], w);
            sa[b0]          = make_float2(u.x + t2.x, u.y + t2.y);
            sa[b0 + half*8] = make_float2(u.x - t2.x, u.y - t2.y);
        }
        __syncthreads();
    }
    #pragma unroll
    for (int it = 0; it < 4; it++) {
        int idx = tid + it*256;
        int cc = idx & 7, k1 = idx >> 3;
        float2 t0 = sa[k1*8 + cc];
        float2 t1 = sa[(128 + k1)*8 + cc];
        float2 t2 = sa[(256 + k1)*8 + cc];
        float2 w1 = tw[k1], w2 = tw[2*k1];
        if (DIR > 0) { w1.y = -w1.y; w2.y = -w2.y; }
        t1 = cmul(t1, w1);
        t2 = cmul(t2, w2);
        const float s3 = DIR * 0.86602540378443864676f;
        float2 w3  = make_float2(-0.5f,  s3);
        float2 w3b = make_float2(-0.5f, -s3);
        float2 a1 = cmul(t1, w3),  a2 = cmul(t2, w3b);
        float2 b1 = cmul(t1, w3b), b2 = cmul(t2, w3);
        sa[k1*8 + cc]         = make_float2(t0.x + t1.x + t2.x, t0.y + t1.y + t2.y);
        sa[(128 + k1)*8 + cc] = make_float2(t0.x + a1.x + a2.x, t0.y + a1.y + a2.y);
        sa[(256 + k1)*8 + cc] = make_float2(t0.x + b1.x + b2.x, t0.y + b1.y + b2.y);
    }
    __syncthreads();
}

// ---------------- forward FFT, rows (4 rows per block) ----------------
__global__ void k_fwd_rows(const float* __restrict__ x) {
    __shared__ float2 sa4[4][384];
    __shared__ float2 tw[384];
    int tid = threadIdx.x;                     // 768
    int rg  = tid / 192;
    int rt  = tid % 192;
    fill_tw(tw, tid, 768);
    int gr = blockIdx.x * 4 + rg;
    int p = gr / 384, h = gr % 384;
    float2* sa = sa4[rg];
    const float* row = x + (size_t)p*NPIX + (size_t)h*384;
    sa[rt]       = make_float2(row[rt],       0.0f);
    sa[rt + 192] = make_float2(row[rt + 192], 0.0f);
    fft384_row<-1>(sa, tw, rt);
    float2* o = g_Tmp + (size_t)p*NPIX + (size_t)h*384;
    o[rt] = sa[rt]; o[rt + 192] = sa[rt + 192];
}

// ---------------- forward FFT, cols (tiled) + fftshift + batch/channel relabel ----------------
__global__ void k_fwd_cols() {
    __shared__ float2 sa[384 * TC];
    __shared__ float2 tw[384];
    int tile = blockIdx.x % 48, p = blockIdx.x / 48;
    int b = p / 3, c = p % 3;
    int w0 = tile * TC;
    int tid = threadIdx.x;                     // 256
    fill_tw(tw, tid, 256);
    for (int i = tid; i < 384*TC; i += 256) {
        int cc = i & 7, t = i >> 3;
        int j = t & 127, n2 = t >> 7;
        int r = __brev((unsigned)j) >> 25;
        int hsrc = 3*r + n2;
        sa[i] = g_Tmp[(size_t)p*NPIX + (size_t)hsrc*384 + w0 + cc];
    }
    __syncthreads();
    fft384_cols8<-1>(sa, tw, tid);
    int pp = ((b + 2) & 3) * 3 + ((c + 1) % 3);
    int wp0 = (w0 + 192) % 384;
    for (int i = tid; i < 384*TC; i += 256) {
        int cc = i & 7, h = i >> 3;
        int hp = (h + 192) % 384;
        g_Y[(size_t)pp*NPIX + (size_t)hp*384 + wp0 + cc] = sa[i];
    }
}

// ---------------- fused attention: one batch-pair per block (grid.y), f32x2 MLP ----------------
__global__ void k_attn(const float* __restrict__ theta, const float* __restrict__ sigma,
                       const float* __restrict__ f0,    const float* __restrict__ theta0,
                       const float* __restrict__ w1,    const float* __restrict__ b1v,
                       const float* __restrict__ w2,    const float* __restrict__ b2v) {
    __shared__ float4 sW1B[64];         // {w1[j][0..2], b1[j]}
    __shared__ ull    sW2D[64*10];      // per j: 9 duplicate-packed w2 (+pad); 80B rows
    __shared__ float  sB2[9];
    __shared__ float  sLF0[27], sI2LS[27], sTH[27], sI2T0[27];
    int tid = threadIdx.x;  // 256
    if (tid < 64) {
        sW1B[tid] = make_float4(w1[tid*3], w1[tid*3+1], w1[tid*3+2], b1v[tid]);
        #pragma unroll
        for (int o = 0; o < 9; o++) {
            unsigned u = __float_as_uint(w2[o*64 + tid]);
            sW2D[tid*10 + o] = (ull)u | ((ull)u << 32);
        }
        sW2D[tid*10 + 9] = 0;
    }
    if (tid < 9)  sB2[tid] = b2v[tid];
    if (tid < 27) {
        sLF0[tid] = logf(f0[tid]);
        float ls = logf(sigma[tid]);
        sI2LS[tid] = 1.0f / (2.0f * ls * ls);
        sTH[tid]   = theta[tid];
        float t0 = theta0[tid];
        sI2T0[tid] = 1.0f / (2.0f * t0 * t0);
    }
    __syncthreads();

    int px = blockIdx.x * 256 + tid;
    if (px >= NPIX) return;
    int bp = blockIdx.y;                // batch pair: batches 2*bp, 2*bp+1

    // phase 1: magnitudes for the 2 batches
    float mag[6];
    #pragma unroll
    for (int bb = 0; bb < 2; bb++)
        #pragma unroll
        for (int d = 0; d < 3; d++) {
            float2 yv = g_Y[(size_t)((2*bp + bb)*3 + d)*NPIX + px];
            mag[bb*3 + d] = sqrtf(yv.x*yv.x + yv.y*yv.y);
        }

    // phase 2: MLP, both batches packed into f32x2 lanes
    ull lgp[9];
    #pragma unroll
    for (int o = 0; o < 9; o++) {
        unsigned u = __float_as_uint(sB2[o]);
        lgp[o] = (ull)u | ((ull)u << 32);
    }
    for (int j = 0; j < 64; j++) {
        float4 wb = sW1B[j];
        float h0 = fmaxf(fmaf(wb.x, mag[0], fmaf(wb.y, mag[1], fmaf(wb.z, mag[2], wb.w))), 0.0f);
        float h1 = fmaxf(fmaf(wb.x, mag[3], fmaf(wb.y, mag[4], fmaf(wb.z, mag[5], wb.w))), 0.0f);
        ull hp;
        PACK2F(hp, h0, h1);
        const ull* wrow = sW2D + j*10;
        ulonglong2 wA = ((const ulonglong2*)wrow)[0];
        ulonglong2 wB = ((const ulonglong2*)wrow)[1];
        ulonglong2 wC = ((const ulonglong2*)wrow)[2];
        ulonglong2 wD = ((const ulonglong2*)wrow)[3];
        ull        w8 = wrow[8];
        FMA_F32X2(lgp[0], hp, wA.x, lgp[0]);
        FMA_F32X2(lgp[1], hp, wA.y, lgp[1]);
        FMA_F32X2(lgp[2], hp, wB.x, lgp[2]);
        FMA_F32X2(lgp[3], hp, wB.y, lgp[3]);
        FMA_F32X2(lgp[4], hp, wC.x, lgp[4]);
        FMA_F32X2(lgp[5], hp, wC.y, lgp[5]);
        FMA_F32X2(lgp[6], hp, wD.x, lgp[6]);
        FMA_F32X2(lgp[7], hp, wD.y, lgp[7]);
        FMA_F32X2(lgp[8], hp, w8,   lgp[8]);
    }

    // geometry (shared by both batches)
    int h = px / 384, w = px % 384;
    float yy = -1.0f + 2.0f * (float)h / 383.0f;
    float xx = -1.0f + 2.0f * (float)w / 383.0f;
    float r   = sqrtf(xx*xx + yy*yy + 1e-6f);
    float phi = atan2f(yy, xx);

    // phase 3+4: per batch: softmax, then on-the-fly Gabor weighting
    #pragma unroll
    for (int bb = 0; bb < 2; bb++) {
        float lg[9];
        #pragma unroll
        for (int o = 0; o < 9; o++) {
            float lo_, hi_;
            unpack2f(lgp[o], lo_, hi_);
            lg[o] = bb ? hi_ : lo_;
        }
        float mx = lg[0];
        #pragma unroll
        for (int o = 1; o < 9; o++) mx = fmaxf(mx, lg[o]);
        float ex[9]; float se = 0.0f;
        #pragma unroll
        for (int o = 0; o < 9; o++) { ex[o] = expf(lg[o] - mx); se += ex[o]; }
        float inv = 1.0f / se;

        float wg[3] = {0.0f, 0.0f, 0.0f};
        #pragma unroll
        for (int o = 0; o < 9; o++) {
            #pragma unroll
            for (int d = 0; d < 3; d++) {
                int i = o*3 + d;
                float L  = logf(r - sLF0[i]);
                float dp = phi - sTH[i];
                float ft = expf(-(L*L*sI2LS[i] + dp*dp*sI2T0[i]));
                wg[d] = fmaf(ex[o], ft, wg[d]);
            }
        }
        int b = 2*bp + bb;
        float2 acc = make_float2(0.0f, 0.0f);
        #pragma unroll
        for (int d = 0; d < 3; d++) {
            float2 yv = g_Y[(size_t)(b*3 + d)*NPIX + px];
            float wgt = wg[d] * inv;
            acc.x = fmaf(yv.x, wgt, acc.x);
            acc.y = fmaf(yv.y, wgt, acc.y);
        }
        g_Att[(size_t)b*NPIX + px] = acc;
    }
}

// ---------------- inverse FFT rows of ifftshift(mask * attended) ----------------
__global__ void k_ifft_rows(const float* __restrict__ band) {
    __shared__ float2 sa[384];
    __shared__ float2 tw[384];
    int bh = blockIdx.x;
    int h = bh % 192, q = bh / 192;
    int ci = q % 3, b2 = (q / 3) & 3, co = q / 12;
    int cos_ = (co + 1) % 3, bs = (b2 + 2) & 3, cis = (ci + 1) % 3;
    int bi = (cos_*3 + cis) * 2;
    int si = (int)floorf((band[bi]     + 1.0f) / 2.0f * 384.0f);
    int ei = (int)floorf((band[bi + 1] + 1.0f) / 2.0f * 384.0f);
    int hs = h + 192;
    if (!((si < ei) && (hs >= si) && (hs < ei))) return;   // zero row: skip entirely

    int tid = threadIdx.x;
    fill_tw(tw, tid, 192);
    const float2* arow = g_Att + (size_t)bs*NPIX + (size_t)hs*384;
    #pragma unroll
    for (int k = 0; k < 2; k++) {
        int w  = tid + k*192;
        int ws = (w + 192) % 384;
        bool on = (ws >= si) && (ws < ei);
        sa[w] = on ? arow[ws] : make_float2(0.0f, 0.0f);
    }
    fft384_row<1>(sa, tw, tid);
    float2* o = g_Tmp + (size_t)q*NPIX + (size_t)h*384;
    o[tid] = sa[tid]; o[tid + 192] = sa[tid + 192];
}

// ---------------- inverse FFT cols (tiled) fused with mix + b1-broadcast write ----------------
__global__ void k_ifft_cols_combine(const float* __restrict__ band,
                                    const float* __restrict__ mixing,
                                    float* __restrict__ out) {
    __shared__ float2 sa[384 * TC];
    __shared__ float2 tw[384];
    int tile = blockIdx.x % 48, q = blockIdx.x / 48;
    int ci = q % 3, b2 = (q / 3) & 3, co = q / 12;
    int cos_ = (co + 1) % 3, cis = (ci + 1) % 3;
    int bi = (cos_*3 + cis) * 2;
    int si = (int)floorf((band[bi]     + 1.0f) / 2.0f * 384.0f);
    int ei = (int)floorf((band[bi + 1] + 1.0f) / 2.0f * 384.0f);
    int h0 = si - 192, h1e = ei - 192;
    int tid = threadIdx.x;                     // 256
    int w0 = tile * TC;
    float mix = mixing[0];
    const float* xsp = g_XSP + (size_t)(b2*3 + ci)*NPIX;
    const size_t NIN = (size_t)36 * NPIX;

    if (si >= ei) {                            // fully-masked plane: x_filtered = 0
        for (int i = tid; i < 384*TC; i += 256) {
            int cc = i & 7, h = i >> 3;
            size_t px = (size_t)h*384 + w0 + cc;
            float val = (1.0f - mix) * xsp[px];
            size_t o = (size_t)q*NPIX + px;
            #pragma unroll
            for (int b1 = 0; b1 < 4; b1++) out[(size_t)b1*NIN + o] = val;
        }
        return;
    }

    fill_tw(tw, tid, 256);
    for (int i = tid; i < 384*TC; i += 256) {
        int cc = i & 7, t = i >> 3;
        int j = t & 127, n2 = t >> 7;
        int r = __brev((unsigned)j) >> 25;
        int hsrc = 3*r + n2;
        float2 v = make_float2(0.0f, 0.0f);
        if (hsrc >= h0 && hsrc < h1e)
            v = g_Tmp[(size_t)q*NPIX + (size_t)hsrc*384 + w0 + cc];
        sa[i] = v;
    }
    __syncthreads();
    fft384_cols8<1>(sa, tw, tid);

    const float sc = 1.0f / (384.0f * 384.0f);
    for (int i = tid; i < 384*TC; i += 256) {
        int cc = i & 7, h = i >> 3;
        size_t px = (size_t)h*384 + w0 + cc;
        float val = mix * (sa[i].x * sc) + (1.0f - mix) * xsp[px];
        size_t o = (size_t)q*NPIX + px;
        #pragma unroll
        for (int b1 = 0; b1 < 4; b1++) out[(size_t)b1*NIN + o] = val;
    }
}

// ---------------- 3x3 spatial conv: shared-tiled, 3 outputs/thread ----------------
__global__ void k_conv(const float* __restrict__ x, const float* __restrict__ cw) {
    __shared__ float sx[3 * 10 * 36];   // 3 cin planes, 10 rows x 34 cols (36 stride)
    __shared__ float sw[81];
    int tid = threadIdx.x;              // 256
    if (tid < 81) sw[tid] = cw[tid];
    int bidx = blockIdx.x;              // 4 * 48 * 12 = 2304
    int twi = bidx % 12, thi = (bidx / 12) % 48, b = bidx / (12 * 48);
    int w0 = twi * 32, h0 = thi * 8;

    for (int i = tid; i < 3 * 340; i += 256) {
        int c = i / 340, rem = i % 340;
        int rr = rem / 34, cc = rem % 34;
        int hh = h0 + rr - 1, ww = w0 + cc - 1;
        float v = 0.0f;
        if (hh >= 0 && hh < 384 && ww >= 0 && ww < 384)
            v = x[(size_t)(b*3 + c)*NPIX + (size_t)hh*384 + ww];
        sx[c*360 + rr*36 + cc] = v;
    }
    __syncthreads();

    int lw = tid % 32, lh = tid / 32;   // 32 x 8 outputs
    float acc0 = 0.0f, acc1 = 0.0f, acc2 = 0.0f;
    #pragma unroll
    for (int c = 0; c < 3; c++) {
        #pragma unroll
        for (int kh = 0; kh < 3; kh++) {
            #pragma unroll
            for (int kw = 0; kw < 3; kw++) {
                float v = sx[c*360 + (lh + kh)*36 + (lw + kw)];
                int ki = c*9 + kh*3 + kw;
                acc0 = fmaf(v, sw[ki],      acc0);
                acc1 = fmaf(v, sw[27 + ki], acc1);
                acc2 = fmaf(v, sw[54 + ki], acc2);
            }
        }
    }
    size_t px = (size_t)(h0 + lh)*384 + (w0 + lw);
    g_XSP[(size_t)(b*3 + 0)*NPIX + px] = acc0;
    g_XSP[(size_t)(b*3 + 1)*NPIX + px] = acc1;
    g_XSP[(size_t)(b*3 + 2)*NPIX + px] = acc2;
}

// ---------------- launch ----------------
extern "C" void kernel_launch(void* const* d_in, const int* in_sizes, int n_in,
                              void* d_out, int out_size) {
    const float* x      = (const float*)d_in[0];
    const float* theta  = (const float*)d_in[1];
    const float* sigma  = (const float*)d_in[2];
    const float* f0     = (const float*)d_in[3];
    const float* theta0 = (const float*)d_in[4];
    const float* w1     = (const float*)d_in[5];
    const float* b1v    = (const float*)d_in[6];
    const float* w2     = (const float*)d_in[7];
    const float* b2v    = (const float*)d_in[8];
    const float* convw  = (const float*)d_in[9];
    const float* mixing = (const float*)d_in[10];
    const float* band   = (const float*)d_in[11];
    float* out = (float*)d_out;

    k_fwd_rows<<<12 * 384 / 4, 768>>>(x);
    k_fwd_cols<<<48 * 12, 256>>>();
    k_attn<<<dim3(NPIX / 256, 2), 256>>>(theta, sigma, f0, theta0, w1, b1v, w2, b2v);
    k_conv<<<4 * 48 * 12, 256>>>(x, convw);
    k_ifft_rows<<<36 * 192, 192>>>(band);
    k_ifft_cols_combine<<<48 * 36, 256>>>(band, mixing, out);
}